// round 6
// baseline (speedup 1.0000x reference)
#include <cuda_runtime.h>
#include <cuda_fp16.h>
#include <cstdint>

#define FEAT   128
#define HID    128
#define HID2   64
#define BM     128
#define THREADS 256
#define MAXN   10000
#define APITCH 136            // halves per row (272B): conflict-free 8-row groups

// smem layout (bytes)
#define SM_A    0                         // 128 x 136 fp16
#define SM_B    (128 * APITCH * 2)        // 64 x 136 fp16
#define SM_PAR  (SM_B + 64 * APITCH * 2)
#define SM_B1   SM_PAR
#define SM_G1   (SM_B1 + 512)
#define SM_BE1  (SM_G1 + 512)
#define SM_B2   (SM_BE1 + 512)
#define SM_G2   (SM_B2 + 256)
#define SM_BE2  (SM_G2 + 256)
#define SM_W3   (SM_BE2 + 256)
#define SM_TOTAL (SM_W3 + 256)

__device__ __align__(16) float  g_Pdrug[MAXN * HID];
__device__ __align__(16) float  g_Pdis [MAXN * HID];
__device__ __align__(16) __half g_W2h[HID2 * HID];   // [n][k], fp16

__device__ __forceinline__ float gelu_fast(float x) {
    const float x2 = x * x;
    const float inner = x * fmaf(0.0356774081f, x2, 0.7978845608f);
    float t;
    asm("tanh.approx.f32 %0, %1;" : "=f"(t) : "f"(inner));
    return 0.5f * x * (1.0f + t);
}

__device__ __forceinline__ uint32_t smem_u32(const void* p) {
    uint32_t a;
    asm("{ .reg .u64 t; cvta.to.shared.u64 t, %1; cvt.u32.u64 %0, t; }" : "=r"(a) : "l"(p));
    return a;
}

// ---------------------------------------------------------------------------
__global__ void w2h_kernel(const float* __restrict__ W2) {
    const int i = blockIdx.x * blockDim.x + threadIdx.x;   // i = n*128 + k
    if (i < HID * HID2) {
        const int n = i >> 7, k = i & 127;
        g_W2h[i] = __float2half_rn(W2[k * HID2 + n]);
    }
}

// ---------------------------------------------------------------------------
__global__ __launch_bounds__(THREADS) void precompute_kernel(
    const float* __restrict__ drug, const float* __restrict__ dis,
    const float* __restrict__ W1, int n_drug, int n_dis)
{
    const int table = blockIdx.y;
    const int n = table ? n_dis : n_drug;
    const float* __restrict__ feat = table ? dis : drug;
    const float* __restrict__ w    = W1 + (table ? (size_t)FEAT * HID : 0);
    float* __restrict__ outp       = table ? g_Pdis : g_Pdrug;

    const int n0 = blockIdx.x * 32;
    if (n0 >= n) return;

    __shared__ float fs[32][FEAT];
    const int tid = threadIdx.x;
    for (int idx = tid; idx < 32 * FEAT; idx += THREADS) {
        int node = idx >> 7, k = idx & 127;
        fs[node][k] = (n0 + node < n) ? feat[(size_t)(n0 + node) * FEAT + k] : 0.0f;
    }
    __syncthreads();

    const int tx = tid & 31, ty = tid >> 5;
    float acc[4][4] = {};
    #pragma unroll 4
    for (int k = 0; k < FEAT; ++k) {
        float wv[4];
        #pragma unroll
        for (int c = 0; c < 4; ++c) wv[c] = w[(size_t)k * HID + tx + 32 * c];
        #pragma unroll
        for (int i = 0; i < 4; ++i) {
            float f = fs[ty * 4 + i][k];
            #pragma unroll
            for (int c = 0; c < 4; ++c) acc[i][c] = fmaf(f, wv[c], acc[i][c]);
        }
    }
    #pragma unroll
    for (int i = 0; i < 4; ++i) {
        int node = n0 + ty * 4 + i;
        if (node < n) {
            #pragma unroll
            for (int c = 0; c < 4; ++c)
                outp[(size_t)node * HID + tx + 32 * c] = acc[i][c];
        }
    }
}

// ---------------------------------------------------------------------------
extern __shared__ char smem_raw[];

__global__ __launch_bounds__(THREADS, 2) void edge_kernel(
    const int* __restrict__ src, const int* __restrict__ dst,
    const float* __restrict__ b1, const float* __restrict__ g1, const float* __restrict__ be1,
    const float* __restrict__ b2, const float* __restrict__ g2, const float* __restrict__ be2,
    const float* __restrict__ W3, const float* __restrict__ b3,
    float* __restrict__ out, int E)
{
    __half* As = (__half*)(smem_raw + SM_A);
    __half* Bs = (__half*)(smem_raw + SM_B);
    float* b1s  = (float*)(smem_raw + SM_B1);
    float* g1s  = (float*)(smem_raw + SM_G1);
    float* be1s = (float*)(smem_raw + SM_BE1);
    float* b2s  = (float*)(smem_raw + SM_B2);
    float* g2s  = (float*)(smem_raw + SM_G2);
    float* be2s = (float*)(smem_raw + SM_BE2);
    float* w3s  = (float*)(smem_raw + SM_W3);

    const int tid = threadIdx.x;
    const int wid = tid >> 5, lane = tid & 31;
    const uint32_t smem_base = smem_u32(smem_raw);

    if (tid < HID)  { b1s[tid] = b1[tid]; g1s[tid] = g1[tid]; be1s[tid] = be1[tid]; }
    if (tid < HID2) { b2s[tid] = b2[tid]; g2s[tid] = g2[tid]; be2s[tid] = be2[tid]; w3s[tid] = W3[tid]; }

    // B tile: vector-copy precomputed fp16 W2^T into pitched smem (4 uint4/thread)
    {
        const uint4* __restrict__ w2v = (const uint4*)g_W2h;   // 16 uint4 per n-row
        #pragma unroll
        for (int i = tid; i < HID2 * 16; i += THREADS) {
            const int n = i >> 4, kq = i & 15;
            *(uint4*)(Bs + n * APITCH + kq * 8) = w2v[i];
        }
    }
    __syncthreads();

    const int e0 = blockIdx.x * BM;

    // ---------------- Phase 1: z1 = Pdrug[s]+Pdis[d]+b1 ; LN ; GELU -> fp16 A
    for (int er = wid; er < BM; er += 8) {
        const int e = e0 + er;
        uint2* dstp = (uint2*)(As + er * APITCH + lane * 4);
        if (e < E) {
            const int s = src[e], d = dst[e];
            const float4 a  = reinterpret_cast<const float4*>(g_Pdrug + (size_t)s * HID)[lane];
            const float4 bq = reinterpret_cast<const float4*>(g_Pdis  + (size_t)d * HID)[lane];
            const float4 bb = reinterpret_cast<const float4*>(b1s)[lane];
            float v[4];
            v[0] = a.x + bq.x + bb.x;
            v[1] = a.y + bq.y + bb.y;
            v[2] = a.z + bq.z + bb.z;
            v[3] = a.w + bq.w + bb.w;
            float s1 = v[0] + v[1] + v[2] + v[3];
            float s2 = v[0]*v[0] + v[1]*v[1] + v[2]*v[2] + v[3]*v[3];
            #pragma unroll
            for (int m = 16; m > 0; m >>= 1) {
                s1 += __shfl_xor_sync(0xffffffffu, s1, m);
                s2 += __shfl_xor_sync(0xffffffffu, s2, m);
            }
            const float mu  = s1 * (1.0f / HID);
            const float var = s2 * (1.0f / HID) - mu * mu;
            const float rs  = rsqrtf(var + 1e-5f);
            const float4 gg = reinterpret_cast<const float4*>(g1s)[lane];
            const float4 ee = reinterpret_cast<const float4*>(be1s)[lane];
            float h0 = gelu_fast((v[0] - mu) * rs * gg.x + ee.x);
            float h1 = gelu_fast((v[1] - mu) * rs * gg.y + ee.y);
            float h2 = gelu_fast((v[2] - mu) * rs * gg.z + ee.z);
            float h3 = gelu_fast((v[3] - mu) * rs * gg.w + ee.w);
            __half2 p0 = __floats2half2_rn(h0, h1);
            __half2 p1 = __floats2half2_rn(h2, h3);
            uint2 pk;
            pk.x = *reinterpret_cast<uint32_t*>(&p0);
            pk.y = *reinterpret_cast<uint32_t*>(&p1);
            *dstp = pk;
        } else {
            uint2 z = {0u, 0u};
            *dstp = z;
        }
    }
    __syncthreads();

    // ---------------- Phase 2: HMMA m16n8k16 with ldmatrix fragment loads ---
    const int r0  = wid * 16;
    const int gid = lane >> 2, tig = lane & 3;

    // A ldsm.x4 address: mat0 rows r0+0..7 @k0, mat1 rows r0+8..15 @k0,
    //                    mat2 rows r0+0..7 @k0+8, mat3 rows +8..15 @k0+8
    const uint32_t a_addr = smem_base + SM_A
        + (uint32_t)((r0 + (lane & 15)) * APITCH + ((lane >> 4) << 3)) * 2u;
    // B ldsm.x4 per q: mats = {nt0@k0, nt0@k0+8, nt1@k0, nt1@k0+8}, nt0=2q, nt1=2q+1
    uint32_t b_addr[4];
    #pragma unroll
    for (int q = 0; q < 4; ++q) {
        const int nrow = q * 16 + ((lane & 16) >> 1) + (lane & 7);
        const int koff = (lane & 8);  // +8 halves for mats 1,3
        b_addr[q] = smem_base + SM_B + (uint32_t)(nrow * APITCH + koff) * 2u;
    }

    float acc[8][4];
    #pragma unroll
    for (int nt = 0; nt < 8; ++nt)
        #pragma unroll
        for (int j = 0; j < 4; ++j) acc[nt][j] = 0.0f;

    #pragma unroll
    for (int kt = 0; kt < 8; ++kt) {
        const uint32_t kb = kt * 32u;   // 16 halves = 32 bytes
        uint32_t a0, a1, a2, a3;
        asm volatile("ldmatrix.sync.aligned.m8n8.x4.shared.b16 {%0,%1,%2,%3}, [%4];"
                     : "=r"(a0), "=r"(a1), "=r"(a2), "=r"(a3) : "r"(a_addr + kb));
        #pragma unroll
        for (int q = 0; q < 4; ++q) {
            uint32_t c0, c1, c2, c3;
            asm volatile("ldmatrix.sync.aligned.m8n8.x4.shared.b16 {%0,%1,%2,%3}, [%4];"
                         : "=r"(c0), "=r"(c1), "=r"(c2), "=r"(c3) : "r"(b_addr[q] + kb));
            asm volatile(
                "mma.sync.aligned.m16n8k16.row.col.f32.f16.f16.f32 "
                "{%0,%1,%2,%3}, {%4,%5,%6,%7}, {%8,%9}, {%0,%1,%2,%3};"
                : "+f"(acc[2*q][0]), "+f"(acc[2*q][1]), "+f"(acc[2*q][2]), "+f"(acc[2*q][3])
                : "r"(a0), "r"(a1), "r"(a2), "r"(a3), "r"(c0), "r"(c1));
            asm volatile(
                "mma.sync.aligned.m16n8k16.row.col.f32.f16.f16.f32 "
                "{%0,%1,%2,%3}, {%4,%5,%6,%7}, {%8,%9}, {%0,%1,%2,%3};"
                : "+f"(acc[2*q+1][0]), "+f"(acc[2*q+1][1]), "+f"(acc[2*q+1][2]), "+f"(acc[2*q+1][3])
                : "r"(a0), "r"(a1), "r"(a2), "r"(a3), "r"(c2), "r"(c3));
        }
    }

    // ---------------- Phase 3: +b2 ; LN(64) ; GELU ; dot(W3)+b3 ------------
    float zA[16], zB[16];
    float s1a = 0.f, s2a = 0.f, s1b = 0.f, s2b = 0.f;
    #pragma unroll
    for (int nt = 0; nt < 8; ++nt) {
        #pragma unroll
        for (int j = 0; j < 2; ++j) {
            const int col = nt * 8 + 2 * tig + j;
            const float bb = b2s[col];
            const float tA = acc[nt][j]     + bb;
            const float tB = acc[nt][2 + j] + bb;
            zA[nt * 2 + j] = tA;
            zB[nt * 2 + j] = tB;
            s1a += tA; s2a += tA * tA;
            s1b += tB; s2b += tB * tB;
        }
    }
    #pragma unroll
    for (int m = 1; m <= 2; m <<= 1) {
        s1a += __shfl_xor_sync(0xffffffffu, s1a, m);
        s2a += __shfl_xor_sync(0xffffffffu, s2a, m);
        s1b += __shfl_xor_sync(0xffffffffu, s1b, m);
        s2b += __shfl_xor_sync(0xffffffffu, s2b, m);
    }
    const float muA = s1a * (1.0f / HID2);
    const float rsA = rsqrtf(s2a * (1.0f / HID2) - muA * muA + 1e-5f);
    const float muB = s1b * (1.0f / HID2);
    const float rsB = rsqrtf(s2b * (1.0f / HID2) - muB * muB + 1e-5f);

    float dotA = 0.f, dotB = 0.f;
    #pragma unroll
    for (int nt = 0; nt < 8; ++nt) {
        #pragma unroll
        for (int j = 0; j < 2; ++j) {
            const int col = nt * 8 + 2 * tig + j;
            const float gg = g2s[col], be = be2s[col], ww = w3s[col];
            dotA = fmaf(gelu_fast((zA[nt*2+j] - muA) * rsA * gg + be), ww, dotA);
            dotB = fmaf(gelu_fast((zB[nt*2+j] - muB) * rsB * gg + be), ww, dotB);
        }
    }
    #pragma unroll
    for (int m = 1; m <= 2; m <<= 1) {
        dotA += __shfl_xor_sync(0xffffffffu, dotA, m);
        dotB += __shfl_xor_sync(0xffffffffu, dotB, m);
    }

    if (tig == 0) {
        const float b3v = b3[0];
        const int eA = e0 + r0 + gid;
        const int eB = eA + 8;
        if (eA < E) out[eA] = dotA + b3v;
        if (eB < E) out[eB] = dotB + b3v;
    }
}

// ---------------------------------------------------------------------------
extern "C" void kernel_launch(void* const* d_in, const int* in_sizes, int n_in,
                              void* d_out, int out_size)
{
    const float* drug = (const float*)d_in[0];
    const float* dis  = (const float*)d_in[1];
    const int*   src  = (const int*)  d_in[2];
    const int*   dst  = (const int*)  d_in[3];
    const float* W1   = (const float*)d_in[4];
    const float* b1   = (const float*)d_in[5];
    const float* g1   = (const float*)d_in[6];
    const float* be1  = (const float*)d_in[7];
    const float* W2   = (const float*)d_in[8];
    const float* b2   = (const float*)d_in[9];
    const float* g2   = (const float*)d_in[10];
    const float* be2  = (const float*)d_in[11];
    const float* W3   = (const float*)d_in[12];
    const float* b3   = (const float*)d_in[13];
    float* out = (float*)d_out;

    const int n_drug = in_sizes[0] / FEAT;
    const int n_dis  = in_sizes[1] / FEAT;
    const int E      = in_sizes[2];

    w2h_kernel<<<(HID * HID2 + 255) / 256, 256>>>(W2);

    const int nmax = n_drug > n_dis ? n_drug : n_dis;
    dim3 pgrid((nmax + 31) / 32, 2);
    precompute_kernel<<<pgrid, THREADS>>>(drug, dis, W1, n_drug, n_dis);

    cudaFuncSetAttribute(edge_kernel, cudaFuncAttributeMaxDynamicSharedMemorySize, SM_TOTAL);
    const int blocks = (E + BM - 1) / BM;
    edge_kernel<<<blocks, THREADS, SM_TOTAL>>>(
        src, dst, b1, g1, be1, b2, g2, be2, W3, b3, out, E);
}

// round 7
// speedup vs baseline: 1.2370x; 1.2370x over previous
#include <cuda_runtime.h>
#include <cuda_fp16.h>
#include <cstdint>

#define FEAT   128
#define HID    128
#define HID2   64
#define BM     128
#define THREADS 256
#define MAXN   10000
#define APITCH 136            // halves per row (272B)

// smem layout (bytes)
#define SM_A    0                         // 128 x 136 fp16
#define SM_B    (128 * APITCH * 2)        // 64 x 136 fp16
#define SM_PAR  (SM_B + 64 * APITCH * 2)
#define SM_B1   SM_PAR
#define SM_G1   (SM_B1 + 512)
#define SM_BE1  (SM_G1 + 512)
#define SM_B2   (SM_BE1 + 512)
#define SM_G2   (SM_B2 + 256)
#define SM_BE2  (SM_G2 + 256)
#define SM_W3   (SM_BE2 + 256)
#define SM_TOTAL (SM_W3 + 256)            // 54784 B

__device__ __align__(16) float  g_Pdrug[MAXN * HID];
__device__ __align__(16) float  g_Pdis [MAXN * HID];
__device__ __align__(16) __half g_W2h[HID2 * HID];   // [n][k], fp16

__device__ __forceinline__ float gelu_fast(float x) {
    const float x2 = x * x;
    const float inner = x * fmaf(0.0356774081f, x2, 0.7978845608f);
    float t;
    asm("tanh.approx.f32 %0, %1;" : "=f"(t) : "f"(inner));
    return 0.5f * x * (1.0f + t);
}

// ---------------------------------------------------------------------------
__global__ void w2h_kernel(const float* __restrict__ W2) {
    const int i = blockIdx.x * blockDim.x + threadIdx.x;   // i = n*128 + k
    if (i < HID * HID2) {
        const int n = i >> 7, k = i & 127;
        g_W2h[i] = __float2half_rn(W2[k * HID2 + n]);
    }
}

// ---------------------------------------------------------------------------
__global__ __launch_bounds__(THREADS) void precompute_kernel(
    const float* __restrict__ drug, const float* __restrict__ dis,
    const float* __restrict__ W1, int n_drug, int n_dis)
{
    const int table = blockIdx.y;
    const int n = table ? n_dis : n_drug;
    const float* __restrict__ feat = table ? dis : drug;
    const float* __restrict__ w    = W1 + (table ? (size_t)FEAT * HID : 0);
    float* __restrict__ outp       = table ? g_Pdis : g_Pdrug;

    const int n0 = blockIdx.x * 32;
    if (n0 >= n) return;

    __shared__ float fs[32][FEAT];
    const int tid = threadIdx.x;
    for (int idx = tid; idx < 32 * FEAT; idx += THREADS) {
        int node = idx >> 7, k = idx & 127;
        fs[node][k] = (n0 + node < n) ? feat[(size_t)(n0 + node) * FEAT + k] : 0.0f;
    }
    __syncthreads();

    const int tx = tid & 31, ty = tid >> 5;
    float acc[4][4] = {};
    #pragma unroll 4
    for (int k = 0; k < FEAT; ++k) {
        float wv[4];
        #pragma unroll
        for (int c = 0; c < 4; ++c) wv[c] = w[(size_t)k * HID + tx + 32 * c];
        #pragma unroll
        for (int i = 0; i < 4; ++i) {
            float f = fs[ty * 4 + i][k];
            #pragma unroll
            for (int c = 0; c < 4; ++c) acc[i][c] = fmaf(f, wv[c], acc[i][c]);
        }
    }
    #pragma unroll
    for (int i = 0; i < 4; ++i) {
        int node = n0 + ty * 4 + i;
        if (node < n) {
            #pragma unroll
            for (int c = 0; c < 4; ++c)
                outp[(size_t)node * HID + tx + 32 * c] = acc[i][c];
        }
    }
}

// ---------------------------------------------------------------------------
extern __shared__ char smem_raw[];

__global__ __launch_bounds__(THREADS, 3) void edge_kernel(
    const int* __restrict__ src, const int* __restrict__ dst,
    const float* __restrict__ b1, const float* __restrict__ g1, const float* __restrict__ be1,
    const float* __restrict__ b2, const float* __restrict__ g2, const float* __restrict__ be2,
    const float* __restrict__ W3, const float* __restrict__ b3,
    float* __restrict__ out, int E)
{
    __half* As = (__half*)(smem_raw + SM_A);
    __half* Bs = (__half*)(smem_raw + SM_B);
    float* b1s  = (float*)(smem_raw + SM_B1);
    float* g1s  = (float*)(smem_raw + SM_G1);
    float* be1s = (float*)(smem_raw + SM_BE1);
    float* b2s  = (float*)(smem_raw + SM_B2);
    float* g2s  = (float*)(smem_raw + SM_G2);
    float* be2s = (float*)(smem_raw + SM_BE2);
    float* w3s  = (float*)(smem_raw + SM_W3);

    const int tid = threadIdx.x;
    const int wid = tid >> 5, lane = tid & 31;

    if (tid < HID)  { b1s[tid] = b1[tid]; g1s[tid] = g1[tid]; be1s[tid] = be1[tid]; }
    if (tid < HID2) { b2s[tid] = b2[tid]; g2s[tid] = g2[tid]; be2s[tid] = be2[tid]; w3s[tid] = W3[tid]; }

    // B tile: vector-copy precomputed fp16 W2^T [n][k] into pitched smem
    {
        const uint4* __restrict__ w2v = (const uint4*)g_W2h;   // 16 uint4 per n-row
        #pragma unroll
        for (int i = tid; i < HID2 * 16; i += THREADS) {
            const int n = i >> 4, kq = i & 15;
            *(uint4*)(Bs + n * APITCH + kq * 8) = w2v[i];
        }
    }
    __syncthreads();

    const int e0 = blockIdx.x * BM;

    // ---------------- Phase 1: z1 = Pdrug[s]+Pdis[d]+b1 ; LN ; GELU -> fp16 A
    for (int er = wid; er < BM; er += 8) {
        const int e = e0 + er;
        uint2* dstp = (uint2*)(As + er * APITCH + lane * 4);
        if (e < E) {
            const int s = src[e], d = dst[e];
            const float4 a  = reinterpret_cast<const float4*>(g_Pdrug + (size_t)s * HID)[lane];
            const float4 bq = reinterpret_cast<const float4*>(g_Pdis  + (size_t)d * HID)[lane];
            const float4 bb = reinterpret_cast<const float4*>(b1s)[lane];
            float v[4];
            v[0] = a.x + bq.x + bb.x;
            v[1] = a.y + bq.y + bb.y;
            v[2] = a.z + bq.z + bb.z;
            v[3] = a.w + bq.w + bb.w;
            float s1 = v[0] + v[1] + v[2] + v[3];
            float s2 = v[0]*v[0] + v[1]*v[1] + v[2]*v[2] + v[3]*v[3];
            #pragma unroll
            for (int m = 16; m > 0; m >>= 1) {
                s1 += __shfl_xor_sync(0xffffffffu, s1, m);
                s2 += __shfl_xor_sync(0xffffffffu, s2, m);
            }
            const float mu  = s1 * (1.0f / HID);
            const float var = s2 * (1.0f / HID) - mu * mu;
            const float rs  = rsqrtf(var + 1e-5f);
            const float4 gg = reinterpret_cast<const float4*>(g1s)[lane];
            const float4 ee = reinterpret_cast<const float4*>(be1s)[lane];
            float h0 = gelu_fast((v[0] - mu) * rs * gg.x + ee.x);
            float h1 = gelu_fast((v[1] - mu) * rs * gg.y + ee.y);
            float h2 = gelu_fast((v[2] - mu) * rs * gg.z + ee.z);
            float h3 = gelu_fast((v[3] - mu) * rs * gg.w + ee.w);
            __half2 p0 = __floats2half2_rn(h0, h1);
            __half2 p1 = __floats2half2_rn(h2, h3);
            uint2 pk;
            pk.x = *reinterpret_cast<uint32_t*>(&p0);
            pk.y = *reinterpret_cast<uint32_t*>(&p1);
            *dstp = pk;
        } else {
            uint2 z = {0u, 0u};
            *dstp = z;
        }
    }
    __syncthreads();

    // ---------------- Phase 2: HMMA m16n8k16, scalar LDS fragment loads ----
    const int r0  = wid * 16;
    const int gid = lane >> 2, tig = lane & 3;

    float acc[8][4];
    #pragma unroll
    for (int nt = 0; nt < 8; ++nt)
        #pragma unroll
        for (int j = 0; j < 4; ++j) acc[nt][j] = 0.0f;

    #pragma unroll
    for (int kt = 0; kt < 8; ++kt) {
        const int k0 = kt * 16;
        const uint32_t* arow0 = (const uint32_t*)(As + (r0 + gid) * APITCH + k0);
        const uint32_t* arow8 = (const uint32_t*)(As + (r0 + gid + 8) * APITCH + k0);
        uint32_t a0 = arow0[tig];
        uint32_t a1 = arow8[tig];
        uint32_t a2 = arow0[tig + 4];
        uint32_t a3 = arow8[tig + 4];
        #pragma unroll
        for (int nt = 0; nt < 8; ++nt) {
            const uint32_t* brow = (const uint32_t*)(Bs + (nt * 8 + gid) * APITCH + k0);
            uint32_t bb0 = brow[tig];
            uint32_t bb1 = brow[tig + 4];
            asm volatile(
                "mma.sync.aligned.m16n8k16.row.col.f32.f16.f16.f32 "
                "{%0,%1,%2,%3}, {%4,%5,%6,%7}, {%8,%9}, {%0,%1,%2,%3};"
                : "+f"(acc[nt][0]), "+f"(acc[nt][1]), "+f"(acc[nt][2]), "+f"(acc[nt][3])
                : "r"(a0), "r"(a1), "r"(a2), "r"(a3), "r"(bb0), "r"(bb1));
        }
    }

    // ---------------- Phase 3: +b2 ; LN(64) ; GELU ; dot(W3)+b3 ------------
    float zA[16], zB[16];
    float s1a = 0.f, s2a = 0.f, s1b = 0.f, s2b = 0.f;
    #pragma unroll
    for (int nt = 0; nt < 8; ++nt) {
        #pragma unroll
        for (int j = 0; j < 2; ++j) {
            const int col = nt * 8 + 2 * tig + j;
            const float bb = b2s[col];
            const float tA = acc[nt][j]     + bb;
            const float tB = acc[nt][2 + j] + bb;
            zA[nt * 2 + j] = tA;
            zB[nt * 2 + j] = tB;
            s1a += tA; s2a += tA * tA;
            s1b += tB; s2b += tB * tB;
        }
    }
    #pragma unroll
    for (int m = 1; m <= 2; m <<= 1) {
        s1a += __shfl_xor_sync(0xffffffffu, s1a, m);
        s2a += __shfl_xor_sync(0xffffffffu, s2a, m);
        s1b += __shfl_xor_sync(0xffffffffu, s1b, m);
        s2b += __shfl_xor_sync(0xffffffffu, s2b, m);
    }
    const float muA = s1a * (1.0f / HID2);
    const float rsA = rsqrtf(s2a * (1.0f / HID2) - muA * muA + 1e-5f);
    const float muB = s1b * (1.0f / HID2);
    const float rsB = rsqrtf(s2b * (1.0f / HID2) - muB * muB + 1e-5f);

    float dotA = 0.f, dotB = 0.f;
    #pragma unroll
    for (int nt = 0; nt < 8; ++nt) {
        #pragma unroll
        for (int j = 0; j < 2; ++j) {
            const int col = nt * 8 + 2 * tig + j;
            const float gg = g2s[col], be = be2s[col], ww = w3s[col];
            dotA = fmaf(gelu_fast((zA[nt*2+j] - muA) * rsA * gg + be), ww, dotA);
            dotB = fmaf(gelu_fast((zB[nt*2+j] - muB) * rsB * gg + be), ww, dotB);
        }
    }
    #pragma unroll
    for (int m = 1; m <= 2; m <<= 1) {
        dotA += __shfl_xor_sync(0xffffffffu, dotA, m);
        dotB += __shfl_xor_sync(0xffffffffu, dotB, m);
    }

    if (tig == 0) {
        const float b3v = b3[0];
        const int eA = e0 + r0 + gid;
        const int eB = eA + 8;
        if (eA < E) out[eA] = dotA + b3v;
        if (eB < E) out[eB] = dotB + b3v;
    }
}

// ---------------------------------------------------------------------------
extern "C" void kernel_launch(void* const* d_in, const int* in_sizes, int n_in,
                              void* d_out, int out_size)
{
    const float* drug = (const float*)d_in[0];
    const float* dis  = (const float*)d_in[1];
    const int*   src  = (const int*)  d_in[2];
    const int*   dst  = (const int*)  d_in[3];
    const float* W1   = (const float*)d_in[4];
    const float* b1   = (const float*)d_in[5];
    const float* g1   = (const float*)d_in[6];
    const float* be1  = (const float*)d_in[7];
    const float* W2   = (const float*)d_in[8];
    const float* b2   = (const float*)d_in[9];
    const float* g2   = (const float*)d_in[10];
    const float* be2  = (const float*)d_in[11];
    const float* W3   = (const float*)d_in[12];
    const float* b3   = (const float*)d_in[13];
    float* out = (float*)d_out;

    const int n_drug = in_sizes[0] / FEAT;
    const int n_dis  = in_sizes[1] / FEAT;
    const int E      = in_sizes[2];

    w2h_kernel<<<(HID * HID2 + 255) / 256, 256>>>(W2);

    const int nmax = n_drug > n_dis ? n_drug : n_dis;
    dim3 pgrid((nmax + 31) / 32, 2);
    precompute_kernel<<<pgrid, THREADS>>>(drug, dis, W1, n_drug, n_dis);

    cudaFuncSetAttribute(edge_kernel, cudaFuncAttributeMaxDynamicSharedMemorySize, SM_TOTAL);
    const int blocks = (E + BM - 1) / BM;
    edge_kernel<<<blocks, THREADS, SM_TOTAL>>>(
        src, dst, b1, g1, be1, b2, g2, be2, W3, b3, out, E);
}

// round 8
// speedup vs baseline: 1.3976x; 1.1298x over previous
#include <cuda_runtime.h>
#include <cuda_fp16.h>
#include <cstdint>

#define FEAT   128
#define HID    128
#define HID2   64
#define BM     128
#define THREADS 256
#define MAXN   10000
#define APITCH 136            // halves per row (272B)

// smem layout (bytes)
#define SM_A    0                         // 128 x 136 fp16
#define SM_B    (128 * APITCH * 2)        // 64 x 136 fp16
#define SM_PAR  (SM_B + 64 * APITCH * 2)
#define SM_B1   SM_PAR
#define SM_G1   (SM_B1 + 512)
#define SM_BE1  (SM_G1 + 512)
#define SM_B2   (SM_BE1 + 512)
#define SM_G2   (SM_B2 + 256)
#define SM_BE2  (SM_G2 + 256)
#define SM_W3   (SM_BE2 + 256)
#define SM_TOTAL (SM_W3 + 256)            // 54784 B

__device__ __align__(16) float  g_Pdrug[MAXN * HID];
__device__ __align__(16) float  g_Pdis [MAXN * HID];
__device__ __align__(16) __half g_W2h[HID2 * HID];   // [n][k], fp16

__device__ __forceinline__ float gelu_fast(float x) {
    const float x2 = x * x;
    const float inner = x * fmaf(0.0356774081f, x2, 0.7978845608f);
    float t;
    asm("tanh.approx.f32 %0, %1;" : "=f"(t) : "f"(inner));
    return 0.5f * x * (1.0f + t);
}

// ---------------------------------------------------------------------------
__global__ void w2h_kernel(const float* __restrict__ W2) {
    const int i = blockIdx.x * blockDim.x + threadIdx.x;   // i = n*128 + k
    if (i < HID * HID2) {
        const int n = i >> 7, k = i & 127;
        g_W2h[i] = __float2half_rn(W2[k * HID2 + n]);
    }
}

// ---------------------------------------------------------------------------
__global__ __launch_bounds__(THREADS) void precompute_kernel(
    const float* __restrict__ drug, const float* __restrict__ dis,
    const float* __restrict__ W1, int n_drug, int n_dis)
{
    const int table = blockIdx.y;
    const int n = table ? n_dis : n_drug;
    const float* __restrict__ feat = table ? dis : drug;
    const float* __restrict__ w    = W1 + (table ? (size_t)FEAT * HID : 0);
    float* __restrict__ outp       = table ? g_Pdis : g_Pdrug;

    const int n0 = blockIdx.x * 32;
    if (n0 >= n) return;

    __shared__ float fs[32][FEAT];
    const int tid = threadIdx.x;
    for (int idx = tid; idx < 32 * FEAT; idx += THREADS) {
        int node = idx >> 7, k = idx & 127;
        fs[node][k] = (n0 + node < n) ? feat[(size_t)(n0 + node) * FEAT + k] : 0.0f;
    }
    __syncthreads();

    const int tx = tid & 31, ty = tid >> 5;
    float acc[4][4] = {};
    #pragma unroll 4
    for (int k = 0; k < FEAT; ++k) {
        float wv[4];
        #pragma unroll
        for (int c = 0; c < 4; ++c) wv[c] = w[(size_t)k * HID + tx + 32 * c];
        #pragma unroll
        for (int i = 0; i < 4; ++i) {
            float f = fs[ty * 4 + i][k];
            #pragma unroll
            for (int c = 0; c < 4; ++c) acc[i][c] = fmaf(f, wv[c], acc[i][c]);
        }
    }
    #pragma unroll
    for (int i = 0; i < 4; ++i) {
        int node = n0 + ty * 4 + i;
        if (node < n) {
            #pragma unroll
            for (int c = 0; c < 4; ++c)
                outp[(size_t)node * HID + tx + 32 * c] = acc[i][c];
        }
    }
}

// ---------------------------------------------------------------------------
extern __shared__ char smem_raw[];

__global__ __launch_bounds__(THREADS, 4) void edge_kernel(
    const int* __restrict__ src, const int* __restrict__ dst,
    const float* __restrict__ b1, const float* __restrict__ g1, const float* __restrict__ be1,
    const float* __restrict__ b2, const float* __restrict__ g2, const float* __restrict__ be2,
    const float* __restrict__ W3, const float* __restrict__ b3,
    float* __restrict__ out, int E)
{
    __half* As = (__half*)(smem_raw + SM_A);
    __half* Bs = (__half*)(smem_raw + SM_B);
    float* b1s  = (float*)(smem_raw + SM_B1);
    float* g1s  = (float*)(smem_raw + SM_G1);
    float* be1s = (float*)(smem_raw + SM_BE1);
    float* b2s  = (float*)(smem_raw + SM_B2);
    float* g2s  = (float*)(smem_raw + SM_G2);
    float* be2s = (float*)(smem_raw + SM_BE2);
    float* w3s  = (float*)(smem_raw + SM_W3);

    const int tid = threadIdx.x;
    const int wid = tid >> 5, lane = tid & 31;

    if (tid < HID)  { b1s[tid] = b1[tid]; g1s[tid] = g1[tid]; be1s[tid] = be1[tid]; }
    if (tid < HID2) { b2s[tid] = b2[tid]; g2s[tid] = g2[tid]; be2s[tid] = be2[tid]; w3s[tid] = W3[tid]; }

    // B tile: vector-copy precomputed fp16 W2^T [n][k] into pitched smem
    {
        const uint4* __restrict__ w2v = (const uint4*)g_W2h;   // 16 uint4 per n-row
        #pragma unroll
        for (int i = tid; i < HID2 * 16; i += THREADS) {
            const int n = i >> 4, kq = i & 15;
            *(uint4*)(Bs + n * APITCH + kq * 8) = w2v[i];
        }
    }
    __syncthreads();

    const int e0 = blockIdx.x * BM;

    // ---------------- Phase 1: z1 = Pdrug[s]+Pdis[d]+b1 ; LN ; GELU -> fp16 A
    {
        // loop-invariant per-lane params, hoisted out of the edge loop
        const float4 bb = reinterpret_cast<const float4*>(b1s)[lane];
        const float4 gg = reinterpret_cast<const float4*>(g1s)[lane];
        const float4 ee = reinterpret_cast<const float4*>(be1s)[lane];
        for (int er = wid; er < BM; er += 8) {
            const int e = e0 + er;
            uint2* dstp = (uint2*)(As + er * APITCH + lane * 4);
            if (e < E) {
                const int s = src[e], d = dst[e];
                const float4 a  = reinterpret_cast<const float4*>(g_Pdrug + (size_t)s * HID)[lane];
                const float4 bq = reinterpret_cast<const float4*>(g_Pdis  + (size_t)d * HID)[lane];
                float v[4];
                v[0] = a.x + bq.x + bb.x;
                v[1] = a.y + bq.y + bb.y;
                v[2] = a.z + bq.z + bb.z;
                v[3] = a.w + bq.w + bb.w;
                float s1 = v[0] + v[1] + v[2] + v[3];
                float s2 = v[0]*v[0] + v[1]*v[1] + v[2]*v[2] + v[3]*v[3];
                #pragma unroll
                for (int m = 16; m > 0; m >>= 1) {
                    s1 += __shfl_xor_sync(0xffffffffu, s1, m);
                    s2 += __shfl_xor_sync(0xffffffffu, s2, m);
                }
                const float mu  = s1 * (1.0f / HID);
                const float var = s2 * (1.0f / HID) - mu * mu;
                const float rs  = rsqrtf(var + 1e-5f);
                float h0 = gelu_fast((v[0] - mu) * rs * gg.x + ee.x);
                float h1 = gelu_fast((v[1] - mu) * rs * gg.y + ee.y);
                float h2 = gelu_fast((v[2] - mu) * rs * gg.z + ee.z);
                float h3 = gelu_fast((v[3] - mu) * rs * gg.w + ee.w);
                __half2 p0 = __floats2half2_rn(h0, h1);
                __half2 p1 = __floats2half2_rn(h2, h3);
                uint2 pk;
                pk.x = *reinterpret_cast<uint32_t*>(&p0);
                pk.y = *reinterpret_cast<uint32_t*>(&p1);
                *dstp = pk;
            } else {
                uint2 z = {0u, 0u};
                *dstp = z;
            }
        }
    }
    __syncthreads();

    // ---------------- Phase 2: HMMA m16n8k16, scalar LDS fragment loads ----
    const int r0  = wid * 16;
    const int gid = lane >> 2, tig = lane & 3;

    float acc[8][4];
    #pragma unroll
    for (int nt = 0; nt < 8; ++nt)
        #pragma unroll
        for (int j = 0; j < 4; ++j) acc[nt][j] = 0.0f;

    #pragma unroll
    for (int kt = 0; kt < 8; ++kt) {
        const int k0 = kt * 16;
        const uint32_t* arow0 = (const uint32_t*)(As + (r0 + gid) * APITCH + k0);
        const uint32_t* arow8 = (const uint32_t*)(As + (r0 + gid + 8) * APITCH + k0);
        uint32_t a0 = arow0[tig];
        uint32_t a1 = arow8[tig];
        uint32_t a2 = arow0[tig + 4];
        uint32_t a3 = arow8[tig + 4];
        #pragma unroll
        for (int nt = 0; nt < 8; ++nt) {
            const uint32_t* brow = (const uint32_t*)(Bs + (nt * 8 + gid) * APITCH + k0);
            uint32_t bb0 = brow[tig];
            uint32_t bb1 = brow[tig + 4];
            asm volatile(
                "mma.sync.aligned.m16n8k16.row.col.f32.f16.f16.f32 "
                "{%0,%1,%2,%3}, {%4,%5,%6,%7}, {%8,%9}, {%0,%1,%2,%3};"
                : "+f"(acc[nt][0]), "+f"(acc[nt][1]), "+f"(acc[nt][2]), "+f"(acc[nt][3])
                : "r"(a0), "r"(a1), "r"(a2), "r"(a3), "r"(bb0), "r"(bb1));
        }
    }

    // ---------------- Phase 3: +b2 (in-place) ; LN(64) ; GELU ; dot(W3)+b3 -
    float s1a = 0.f, s2a = 0.f, s1b = 0.f, s2b = 0.f;
    #pragma unroll
    for (int nt = 0; nt < 8; ++nt) {
        #pragma unroll
        for (int j = 0; j < 2; ++j) {
            const float bb = b2s[nt * 8 + 2 * tig + j];
            acc[nt][j]     += bb;
            acc[nt][2 + j] += bb;
            const float tA = acc[nt][j];
            const float tB = acc[nt][2 + j];
            s1a += tA; s2a += tA * tA;
            s1b += tB; s2b += tB * tB;
        }
    }
    #pragma unroll
    for (int m = 1; m <= 2; m <<= 1) {
        s1a += __shfl_xor_sync(0xffffffffu, s1a, m);
        s2a += __shfl_xor_sync(0xffffffffu, s2a, m);
        s1b += __shfl_xor_sync(0xffffffffu, s1b, m);
        s2b += __shfl_xor_sync(0xffffffffu, s2b, m);
    }
    const float muA = s1a * (1.0f / HID2);
    const float rsA = rsqrtf(s2a * (1.0f / HID2) - muA * muA + 1e-5f);
    const float muB = s1b * (1.0f / HID2);
    const float rsB = rsqrtf(s2b * (1.0f / HID2) - muB * muB + 1e-5f);

    float dotA = 0.f, dotB = 0.f;
    #pragma unroll
    for (int nt = 0; nt < 8; ++nt) {
        #pragma unroll
        for (int j = 0; j < 2; ++j) {
            const int col = nt * 8 + 2 * tig + j;
            const float gg = g2s[col], be = be2s[col], ww = w3s[col];
            dotA = fmaf(gelu_fast((acc[nt][j]     - muA) * rsA * gg + be), ww, dotA);
            dotB = fmaf(gelu_fast((acc[nt][2 + j] - muB) * rsB * gg + be), ww, dotB);
        }
    }
    #pragma unroll
    for (int m = 1; m <= 2; m <<= 1) {
        dotA += __shfl_xor_sync(0xffffffffu, dotA, m);
        dotB += __shfl_xor_sync(0xffffffffu, dotB, m);
    }

    if (tig == 0) {
        const float b3v = b3[0];
        const int eA = e0 + r0 + gid;
        const int eB = eA + 8;
        if (eA < E) out[eA] = dotA + b3v;
        if (eB < E) out[eB] = dotB + b3v;
    }
}

// ---------------------------------------------------------------------------
extern "C" void kernel_launch(void* const* d_in, const int* in_sizes, int n_in,
                              void* d_out, int out_size)
{
    const float* drug = (const float*)d_in[0];
    const float* dis  = (const float*)d_in[1];
    const int*   src  = (const int*)  d_in[2];
    const int*   dst  = (const int*)  d_in[3];
    const float* W1   = (const float*)d_in[4];
    const float* b1   = (const float*)d_in[5];
    const float* g1   = (const float*)d_in[6];
    const float* be1  = (const float*)d_in[7];
    const float* W2   = (const float*)d_in[8];
    const float* b2   = (const float*)d_in[9];
    const float* g2   = (const float*)d_in[10];
    const float* be2  = (const float*)d_in[11];
    const float* W3   = (const float*)d_in[12];
    const float* b3   = (const float*)d_in[13];
    float* out = (float*)d_out;

    const int n_drug = in_sizes[0] / FEAT;
    const int n_dis  = in_sizes[1] / FEAT;
    const int E      = in_sizes[2];

    w2h_kernel<<<(HID * HID2 + 255) / 256, 256>>>(W2);

    const int nmax = n_drug > n_dis ? n_drug : n_dis;
    dim3 pgrid((nmax + 31) / 32, 2);
    precompute_kernel<<<pgrid, THREADS>>>(drug, dis, W1, n_drug, n_dis);

    cudaFuncSetAttribute(edge_kernel, cudaFuncAttributeMaxDynamicSharedMemorySize, SM_TOTAL);
    const int blocks = (E + BM - 1) / BM;
    edge_kernel<<<blocks, THREADS, SM_TOTAL>>>(
        src, dst, b1, g1, be1, b2, g2, be2, W3, b3, out, E);
}

// round 9
// speedup vs baseline: 1.4674x; 1.0499x over previous
#include <cuda_runtime.h>
#include <cuda_fp16.h>
#include <cstdint>

#define FEAT   128
#define HID    128
#define HID2   64
#define BM     128
#define THREADS 256
#define MAXN   10000
#define APITCH 136            // halves per row (272B) for the A tile

// smem layout (bytes)
#define SM_A    0                         // 128 x 136 fp16 = 34816
#define SM_BP   (128 * APITCH * 2)        // fragment-ready B: 16384
#define SM_PAR  (SM_BP + 16384)
#define SM_B1   SM_PAR
#define SM_G1   (SM_B1 + 512)
#define SM_BE1  (SM_G1 + 512)
#define SM_B2   (SM_BE1 + 512)
#define SM_G2   (SM_B2 + 256)
#define SM_BE2  (SM_G2 + 256)
#define SM_W3   (SM_BE2 + 256)
#define SM_TOTAL (SM_W3 + 256)            // 53760 B

__device__ __align__(16) float    g_Pdrug[MAXN * HID];
__device__ __align__(16) float    g_Pdis [MAXN * HID];
// B fragments in HMMA order: [(nt*8+kt)*32 + lane] -> uint2 {b0, b1}
__device__ __align__(16) uint32_t g_W2p[8 * 8 * 32 * 2];

__device__ __forceinline__ float gelu_fast(float x) {
    const float x2 = x * x;
    const float inner = x * fmaf(0.0356774081f, x2, 0.7978845608f);
    float t;
    asm("tanh.approx.f32 %0, %1;" : "=f"(t) : "f"(inner));
    return 0.5f * x * (1.0f + t);
}

// ---------------------------------------------------------------------------
// Permute W2 [k=128][n=64] fp32 -> fragment-ready fp16 words.
// word (nt, kt, lane=(gid,tig), w): halves { W2T[n][kb], W2T[n][kb+1] },
//   n = nt*8+gid, kb = kt*16 + (w ? 8 : 0) + 2*tig,  W2T[n][k] = W2[k*64+n].
// ---------------------------------------------------------------------------
__global__ void w2p_kernel(const float* __restrict__ W2) {
    const int i = blockIdx.x * blockDim.x + threadIdx.x;   // 0..4095
    if (i < 4096) {
        const int w    = i & 1;
        const int lane = (i >> 1) & 31;
        const int kt   = (i >> 6) & 7;
        const int nt   = i >> 9;
        const int gid  = lane >> 2, tig = lane & 3;
        const int n    = nt * 8 + gid;
        const int kb   = kt * 16 + (w ? 8 : 0) + 2 * tig;
        const __half h0 = __float2half_rn(W2[kb * HID2 + n]);
        const __half h1 = __float2half_rn(W2[(kb + 1) * HID2 + n]);
        uint32_t word = ((uint32_t)*(const uint16_t*)&h1 << 16) | *(const uint16_t*)&h0;
        g_W2p[((nt * 8 + kt) * 32 + lane) * 2 + w] = word;
    }
}

// ---------------------------------------------------------------------------
__global__ __launch_bounds__(THREADS) void precompute_kernel(
    const float* __restrict__ drug, const float* __restrict__ dis,
    const float* __restrict__ W1, int n_drug, int n_dis)
{
    const int table = blockIdx.y;
    const int n = table ? n_dis : n_drug;
    const float* __restrict__ feat = table ? dis : drug;
    const float* __restrict__ w    = W1 + (table ? (size_t)FEAT * HID : 0);
    float* __restrict__ outp       = table ? g_Pdis : g_Pdrug;

    const int n0 = blockIdx.x * 32;
    if (n0 >= n) return;

    __shared__ float fs[32][FEAT];
    const int tid = threadIdx.x;
    for (int idx = tid; idx < 32 * FEAT; idx += THREADS) {
        int node = idx >> 7, k = idx & 127;
        fs[node][k] = (n0 + node < n) ? feat[(size_t)(n0 + node) * FEAT + k] : 0.0f;
    }
    __syncthreads();

    const int tx = tid & 31, ty = tid >> 5;
    float acc[4][4] = {};
    #pragma unroll 4
    for (int k = 0; k < FEAT; ++k) {
        float wv[4];
        #pragma unroll
        for (int c = 0; c < 4; ++c) wv[c] = w[(size_t)k * HID + tx + 32 * c];
        #pragma unroll
        for (int i = 0; i < 4; ++i) {
            float f = fs[ty * 4 + i][k];
            #pragma unroll
            for (int c = 0; c < 4; ++c) acc[i][c] = fmaf(f, wv[c], acc[i][c]);
        }
    }
    #pragma unroll
    for (int i = 0; i < 4; ++i) {
        int node = n0 + ty * 4 + i;
        if (node < n) {
            #pragma unroll
            for (int c = 0; c < 4; ++c)
                outp[(size_t)node * HID + tx + 32 * c] = acc[i][c];
        }
    }
}

// ---------------------------------------------------------------------------
extern __shared__ char smem_raw[];

__global__ __launch_bounds__(THREADS, 4) void edge_kernel(
    const int* __restrict__ src, const int* __restrict__ dst,
    const float* __restrict__ b1, const float* __restrict__ g1, const float* __restrict__ be1,
    const float* __restrict__ b2, const float* __restrict__ g2, const float* __restrict__ be2,
    const float* __restrict__ W3, const float* __restrict__ b3,
    float* __restrict__ out, int E)
{
    __half* As   = (__half*)(smem_raw + SM_A);
    uint2*  Bp   = (uint2*)(smem_raw + SM_BP);
    float* b1s  = (float*)(smem_raw + SM_B1);
    float* g1s  = (float*)(smem_raw + SM_G1);
    float* be1s = (float*)(smem_raw + SM_BE1);
    float* b2s  = (float*)(smem_raw + SM_B2);
    float* g2s  = (float*)(smem_raw + SM_G2);
    float* be2s = (float*)(smem_raw + SM_BE2);
    float* w3s  = (float*)(smem_raw + SM_W3);

    const int tid = threadIdx.x;
    const int wid = tid >> 5, lane = tid & 31;

    if (tid < HID)  { b1s[tid] = b1[tid]; g1s[tid] = g1[tid]; be1s[tid] = be1[tid]; }
    if (tid < HID2) { b2s[tid] = b2[tid]; g2s[tid] = g2[tid]; be2s[tid] = be2[tid]; w3s[tid] = W3[tid]; }

    // copy fragment-ready B (16 KB) with uint4 vectors
    {
        const uint4* __restrict__ w2v = (const uint4*)g_W2p;   // 1024 uint4
        #pragma unroll
        for (int i = tid; i < 1024; i += THREADS)
            ((uint4*)Bp)[i] = w2v[i];
    }
    __syncthreads();

    const int e0 = blockIdx.x * BM;

    // ---------------- Phase 1: warp-local rows wid*16 .. wid*16+15 ---------
    {
        const float4 bb = reinterpret_cast<const float4*>(b1s)[lane];
        const float4 gg = reinterpret_cast<const float4*>(g1s)[lane];
        const float4 ee = reinterpret_cast<const float4*>(be1s)[lane];
        const int rbase = wid * 16;
        #pragma unroll 2
        for (int i = 0; i < 16; ++i) {
            const int er = rbase + i;
            const int e = e0 + er;
            uint2* dstp = (uint2*)(As + er * APITCH + lane * 4);
            if (e < E) {
                const int s = src[e], d = dst[e];
                const float4 a  = reinterpret_cast<const float4*>(g_Pdrug + (size_t)s * HID)[lane];
                const float4 bq = reinterpret_cast<const float4*>(g_Pdis  + (size_t)d * HID)[lane];
                float v[4];
                v[0] = a.x + bq.x + bb.x;
                v[1] = a.y + bq.y + bb.y;
                v[2] = a.z + bq.z + bb.z;
                v[3] = a.w + bq.w + bb.w;
                float s1 = v[0] + v[1] + v[2] + v[3];
                float s2 = v[0]*v[0] + v[1]*v[1] + v[2]*v[2] + v[3]*v[3];
                #pragma unroll
                for (int m = 16; m > 0; m >>= 1) {
                    s1 += __shfl_xor_sync(0xffffffffu, s1, m);
                    s2 += __shfl_xor_sync(0xffffffffu, s2, m);
                }
                const float mu  = s1 * (1.0f / HID);
                const float var = s2 * (1.0f / HID) - mu * mu;
                const float rs  = rsqrtf(var + 1e-5f);
                float h0 = gelu_fast((v[0] - mu) * rs * gg.x + ee.x);
                float h1 = gelu_fast((v[1] - mu) * rs * gg.y + ee.y);
                float h2 = gelu_fast((v[2] - mu) * rs * gg.z + ee.z);
                float h3 = gelu_fast((v[3] - mu) * rs * gg.w + ee.w);
                __half2 p0 = __floats2half2_rn(h0, h1);
                __half2 p1 = __floats2half2_rn(h2, h3);
                uint2 pk;
                pk.x = *reinterpret_cast<uint32_t*>(&p0);
                pk.y = *reinterpret_cast<uint32_t*>(&p1);
                *dstp = pk;
            } else {
                uint2 z = {0u, 0u};
                *dstp = z;
            }
        }
    }
    __syncwarp();   // A rows are warp-private; no block barrier needed

    // ---------------- Phase 2: HMMA m16n8k16; A scalar LDS, B LDS.64 -------
    const int r0  = wid * 16;
    const int gid = lane >> 2, tig = lane & 3;

    float acc[8][4];
    #pragma unroll
    for (int nt = 0; nt < 8; ++nt)
        #pragma unroll
        for (int j = 0; j < 4; ++j) acc[nt][j] = 0.0f;

    #pragma unroll
    for (int kt = 0; kt < 8; ++kt) {
        const int k0 = kt * 16;
        const uint32_t* arow0 = (const uint32_t*)(As + (r0 + gid) * APITCH + k0);
        const uint32_t* arow8 = (const uint32_t*)(As + (r0 + gid + 8) * APITCH + k0);
        uint32_t a0 = arow0[tig];
        uint32_t a1 = arow8[tig];
        uint32_t a2 = arow0[tig + 4];
        uint32_t a3 = arow8[tig + 4];
        #pragma unroll
        for (int nt = 0; nt < 8; ++nt) {
            const uint2 bw = Bp[(nt * 8 + kt) * 32 + lane];
            asm volatile(
                "mma.sync.aligned.m16n8k16.row.col.f32.f16.f16.f32 "
                "{%0,%1,%2,%3}, {%4,%5,%6,%7}, {%8,%9}, {%0,%1,%2,%3};"
                : "+f"(acc[nt][0]), "+f"(acc[nt][1]), "+f"(acc[nt][2]), "+f"(acc[nt][3])
                : "r"(a0), "r"(a1), "r"(a2), "r"(a3), "r"(bw.x), "r"(bw.y));
        }
    }

    // ---------------- Phase 3: +b2 (in acc) ; LN(64) ; GELU ; dot(W3)+b3 ---
    float s1a = 0.f, s2a = 0.f, s1b = 0.f, s2b = 0.f;
    #pragma unroll
    for (int nt = 0; nt < 8; ++nt) {
        #pragma unroll
        for (int j = 0; j < 2; ++j) {
            const float bb = b2s[nt * 8 + 2 * tig + j];
            acc[nt][j]     += bb;
            acc[nt][2 + j] += bb;
            const float tA = acc[nt][j];
            const float tB = acc[nt][2 + j];
            s1a += tA; s2a += tA * tA;
            s1b += tB; s2b += tB * tB;
        }
    }
    #pragma unroll
    for (int m = 1; m <= 2; m <<= 1) {
        s1a += __shfl_xor_sync(0xffffffffu, s1a, m);
        s2a += __shfl_xor_sync(0xffffffffu, s2a, m);
        s1b += __shfl_xor_sync(0xffffffffu, s1b, m);
        s2b += __shfl_xor_sync(0xffffffffu, s2b, m);
    }
    const float muA = s1a * (1.0f / HID2);
    const float rsA = rsqrtf(s2a * (1.0f / HID2) - muA * muA + 1e-5f);
    const float muB = s1b * (1.0f / HID2);
    const float rsB = rsqrtf(s2b * (1.0f / HID2) - muB * muB + 1e-5f);

    float dotA = 0.f, dotB = 0.f;
    #pragma unroll
    for (int nt = 0; nt < 8; ++nt) {
        #pragma unroll
        for (int j = 0; j < 2; ++j) {
            const int col = nt * 8 + 2 * tig + j;
            const float gg = g2s[col], be = be2s[col], ww = w3s[col];
            dotA = fmaf(gelu_fast((acc[nt][j]     - muA) * rsA * gg + be), ww, dotA);
            dotB = fmaf(gelu_fast((acc[nt][2 + j] - muB) * rsB * gg + be), ww, dotB);
        }
    }
    #pragma unroll
    for (int m = 1; m <= 2; m <<= 1) {
        dotA += __shfl_xor_sync(0xffffffffu, dotA, m);
        dotB += __shfl_xor_sync(0xffffffffu, dotB, m);
    }

    if (tig == 0) {
        const float b3v = b3[0];
        const int eA = e0 + r0 + gid;
        const int eB = eA + 8;
        if (eA < E) out[eA] = dotA + b3v;
        if (eB < E) out[eB] = dotB + b3v;
    }
}

// ---------------------------------------------------------------------------
extern "C" void kernel_launch(void* const* d_in, const int* in_sizes, int n_in,
                              void* d_out, int out_size)
{
    const float* drug = (const float*)d_in[0];
    const float* dis  = (const float*)d_in[1];
    const int*   src  = (const int*)  d_in[2];
    const int*   dst  = (const int*)  d_in[3];
    const float* W1   = (const float*)d_in[4];
    const float* b1   = (const float*)d_in[5];
    const float* g1   = (const float*)d_in[6];
    const float* be1  = (const float*)d_in[7];
    const float* W2   = (const float*)d_in[8];
    const float* b2   = (const float*)d_in[9];
    const float* g2   = (const float*)d_in[10];
    const float* be2  = (const float*)d_in[11];
    const float* W3   = (const float*)d_in[12];
    const float* b3   = (const float*)d_in[13];
    float* out = (float*)d_out;

    const int n_drug = in_sizes[0] / FEAT;
    const int n_dis  = in_sizes[1] / FEAT;
    const int E      = in_sizes[2];

    w2p_kernel<<<16, 256>>>(W2);

    const int nmax = n_drug > n_dis ? n_drug : n_dis;
    dim3 pgrid((nmax + 31) / 32, 2);
    precompute_kernel<<<pgrid, THREADS>>>(drug, dis, W1, n_drug, n_dis);

    cudaFuncSetAttribute(edge_kernel, cudaFuncAttributeMaxDynamicSharedMemorySize, SM_TOTAL);
    const int blocks = (E + BM - 1) / BM;
    edge_kernel<<<blocks, THREADS, SM_TOTAL>>>(
        src, dst, b1, g1, be1, b2, g2, be2, W3, b3, out, E);
}

// round 10
// speedup vs baseline: 1.7162x; 1.1695x over previous
#include <cuda_runtime.h>
#include <cuda_fp16.h>
#include <cstdint>

#define FEAT   128
#define HID    128
#define HID2   64
#define BM     128
#define THREADS 256
#define MAXN   10000
#define APITCH 136            // halves per row (272B) for the A tile

// smem layout (bytes)
#define SM_A    0                         // 128 x 136 fp16 = 34816
#define SM_BP   (128 * APITCH * 2)        // fragment-ready B: 16384
#define SM_PAR  (SM_BP + 16384)
#define SM_B1   SM_PAR
#define SM_G1   (SM_B1 + 512)
#define SM_BE1  (SM_G1 + 512)
#define SM_B2   (SM_BE1 + 512)
#define SM_G2   (SM_B2 + 256)
#define SM_BE2  (SM_G2 + 256)
#define SM_W3   (SM_BE2 + 256)
#define SM_TOTAL (SM_W3 + 256)            // 53760 B

__device__ __align__(16) float    g_Pdrug[MAXN * HID];
__device__ __align__(16) float    g_Pdis [MAXN * HID];
// B fragments in HMMA order: [(nt*8+kt)*32 + lane] -> uint2 {b0, b1}
__device__ __align__(16) uint32_t g_W2p[8 * 8 * 32 * 2];

__device__ __forceinline__ float gelu_fast(float x) {
    const float x2 = x * x;
    const float inner = x * fmaf(0.0356774081f, x2, 0.7978845608f);
    float t;
    asm("tanh.approx.f32 %0, %1;" : "=f"(t) : "f"(inner));
    return 0.5f * x * (1.0f + t);
}

// ---------------------------------------------------------------------------
__global__ void w2p_kernel(const float* __restrict__ W2) {
    const int i = blockIdx.x * blockDim.x + threadIdx.x;   // 0..4095
    if (i < 4096) {
        const int w    = i & 1;
        const int lane = (i >> 1) & 31;
        const int kt   = (i >> 6) & 7;
        const int nt   = i >> 9;
        const int gid  = lane >> 2, tig = lane & 3;
        const int n    = nt * 8 + gid;
        const int kb   = kt * 16 + (w ? 8 : 0) + 2 * tig;
        const __half h0 = __float2half_rn(W2[kb * HID2 + n]);
        const __half h1 = __float2half_rn(W2[(kb + 1) * HID2 + n]);
        uint32_t word = ((uint32_t)*(const uint16_t*)&h1 << 16) | *(const uint16_t*)&h0;
        g_W2p[((nt * 8 + kt) * 32 + lane) * 2 + w] = word;
    }
}

// ---------------------------------------------------------------------------
__global__ __launch_bounds__(THREADS) void precompute_kernel(
    const float* __restrict__ drug, const float* __restrict__ dis,
    const float* __restrict__ W1, int n_drug, int n_dis)
{
    const int table = blockIdx.y;
    const int n = table ? n_dis : n_drug;
    const float* __restrict__ feat = table ? dis : drug;
    const float* __restrict__ w    = W1 + (table ? (size_t)FEAT * HID : 0);
    float* __restrict__ outp       = table ? g_Pdis : g_Pdrug;

    const int n0 = blockIdx.x * 32;
    if (n0 >= n) return;

    __shared__ float fs[32][FEAT];
    const int tid = threadIdx.x;
    for (int idx = tid; idx < 32 * FEAT; idx += THREADS) {
        int node = idx >> 7, k = idx & 127;
        fs[node][k] = (n0 + node < n) ? feat[(size_t)(n0 + node) * FEAT + k] : 0.0f;
    }
    __syncthreads();

    const int tx = tid & 31, ty = tid >> 5;
    float acc[4][4] = {};
    #pragma unroll 4
    for (int k = 0; k < FEAT; ++k) {
        float wv[4];
        #pragma unroll
        for (int c = 0; c < 4; ++c) wv[c] = w[(size_t)k * HID + tx + 32 * c];
        #pragma unroll
        for (int i = 0; i < 4; ++i) {
            float f = fs[ty * 4 + i][k];
            #pragma unroll
            for (int c = 0; c < 4; ++c) acc[i][c] = fmaf(f, wv[c], acc[i][c]);
        }
    }
    #pragma unroll
    for (int i = 0; i < 4; ++i) {
        int node = n0 + ty * 4 + i;
        if (node < n) {
            #pragma unroll
            for (int c = 0; c < 4; ++c)
                outp[(size_t)node * HID + tx + 32 * c] = acc[i][c];
        }
    }
}

// ---------------------------------------------------------------------------
extern __shared__ char smem_raw[];

__global__ __launch_bounds__(THREADS, 4) void edge_kernel(
    const int* __restrict__ src, const int* __restrict__ dst,
    const float* __restrict__ b1, const float* __restrict__ g1, const float* __restrict__ be1,
    const float* __restrict__ b2, const float* __restrict__ g2, const float* __restrict__ be2,
    const float* __restrict__ W3, const float* __restrict__ b3,
    float* __restrict__ out, int E)
{
    __half* As   = (__half*)(smem_raw + SM_A);
    uint2*  Bp   = (uint2*)(smem_raw + SM_BP);
    float* b1s  = (float*)(smem_raw + SM_B1);
    float* g1s  = (float*)(smem_raw + SM_G1);
    float* be1s = (float*)(smem_raw + SM_BE1);
    float* b2s  = (float*)(smem_raw + SM_B2);
    float* g2s  = (float*)(smem_raw + SM_G2);
    float* be2s = (float*)(smem_raw + SM_BE2);
    float* w3s  = (float*)(smem_raw + SM_W3);

    const int tid = threadIdx.x;
    const int wid = tid >> 5, lane = tid & 31;

    if (tid < HID)  { b1s[tid] = b1[tid]; g1s[tid] = g1[tid]; be1s[tid] = be1[tid]; }
    if (tid < HID2) { b2s[tid] = b2[tid]; g2s[tid] = g2[tid]; be2s[tid] = be2[tid]; w3s[tid] = W3[tid]; }

    // copy fragment-ready B (16 KB) with uint4 vectors
    {
        const uint4* __restrict__ w2v = (const uint4*)g_W2p;   // 1024 uint4
        #pragma unroll
        for (int i = tid; i < 1024; i += THREADS)
            ((uint4*)Bp)[i] = w2v[i];
    }
    __syncthreads();

    const int e0 = blockIdx.x * BM;
    const int r0 = wid * 16;

    // ---------------- Phase 1: warp-local rows r0 .. r0+15 -----------------
    {
        // Batch-load this warp's 16 src + 16 dst indices in ONE coalesced LDG.
        // lanes 0-15: src[e0+r0+lane]; lanes 16-31: dst[e0+r0+lane-16]
        int eidx = e0 + r0 + (lane & 15);
        if (eidx >= E) eidx = E - 1;                 // clamp (finite garbage ok)
        const int idx32 = (lane < 16) ? src[eidx] : dst[eidx];

        const float4 bb = reinterpret_cast<const float4*>(b1s)[lane];
        const float4 gg = reinterpret_cast<const float4*>(g1s)[lane];
        const float4 ee = reinterpret_cast<const float4*>(be1s)[lane];

        #pragma unroll
        for (int i = 0; i < 16; i += 2) {
            // indices for both pipelined rows, from the batched load
            const int s0 = __shfl_sync(0xffffffffu, idx32, i);
            const int d0 = __shfl_sync(0xffffffffu, idx32, 16 + i);
            const int s1 = __shfl_sync(0xffffffffu, idx32, i + 1);
            const int d1 = __shfl_sync(0xffffffffu, idx32, 16 + i + 1);

            // issue all 4 gathers before consuming (2-row MLP)
            const float4 a0 = reinterpret_cast<const float4*>(g_Pdrug + (size_t)s0 * HID)[lane];
            const float4 q0 = reinterpret_cast<const float4*>(g_Pdis  + (size_t)d0 * HID)[lane];
            const float4 a1 = reinterpret_cast<const float4*>(g_Pdrug + (size_t)s1 * HID)[lane];
            const float4 q1 = reinterpret_cast<const float4*>(g_Pdis  + (size_t)d1 * HID)[lane];

            #pragma unroll
            for (int r = 0; r < 2; ++r) {
                const float4 aa = r ? a1 : a0;
                const float4 qq = r ? q1 : q0;
                float v[4];
                v[0] = aa.x + qq.x + bb.x;
                v[1] = aa.y + qq.y + bb.y;
                v[2] = aa.z + qq.z + bb.z;
                v[3] = aa.w + qq.w + bb.w;
                float s1r = v[0] + v[1] + v[2] + v[3];
                float s2r = v[0]*v[0] + v[1]*v[1] + v[2]*v[2] + v[3]*v[3];
                #pragma unroll
                for (int m = 16; m > 0; m >>= 1) {
                    s1r += __shfl_xor_sync(0xffffffffu, s1r, m);
                    s2r += __shfl_xor_sync(0xffffffffu, s2r, m);
                }
                const float mu  = s1r * (1.0f / HID);
                const float var = s2r * (1.0f / HID) - mu * mu;
                const float rs  = rsqrtf(var + 1e-5f);
                float h0 = gelu_fast((v[0] - mu) * rs * gg.x + ee.x);
                float h1 = gelu_fast((v[1] - mu) * rs * gg.y + ee.y);
                float h2 = gelu_fast((v[2] - mu) * rs * gg.z + ee.z);
                float h3 = gelu_fast((v[3] - mu) * rs * gg.w + ee.w);
                __half2 p0 = __floats2half2_rn(h0, h1);
                __half2 p1 = __floats2half2_rn(h2, h3);
                uint2 pk;
                pk.x = *reinterpret_cast<uint32_t*>(&p0);
                pk.y = *reinterpret_cast<uint32_t*>(&p1);
                *(uint2*)(As + (r0 + i + r) * APITCH + lane * 4) = pk;
            }
        }
    }
    __syncwarp();   // A rows are warp-private

    // ---------------- Phase 2: HMMA m16n8k16; A scalar LDS, B LDS.64 -------
    const int gid = lane >> 2, tig = lane & 3;

    float acc[8][4];
    #pragma unroll
    for (int nt = 0; nt < 8; ++nt)
        #pragma unroll
        for (int j = 0; j < 4; ++j) acc[nt][j] = 0.0f;

    #pragma unroll
    for (int kt = 0; kt < 8; ++kt) {
        const int k0 = kt * 16;
        const uint32_t* arow0 = (const uint32_t*)(As + (r0 + gid) * APITCH + k0);
        const uint32_t* arow8 = (const uint32_t*)(As + (r0 + gid + 8) * APITCH + k0);
        uint32_t a0 = arow0[tig];
        uint32_t a1 = arow8[tig];
        uint32_t a2 = arow0[tig + 4];
        uint32_t a3 = arow8[tig + 4];
        #pragma unroll
        for (int nt = 0; nt < 8; ++nt) {
            const uint2 bw = Bp[(nt * 8 + kt) * 32 + lane];
            asm volatile(
                "mma.sync.aligned.m16n8k16.row.col.f32.f16.f16.f32 "
                "{%0,%1,%2,%3}, {%4,%5,%6,%7}, {%8,%9}, {%0,%1,%2,%3};"
                : "+f"(acc[nt][0]), "+f"(acc[nt][1]), "+f"(acc[nt][2]), "+f"(acc[nt][3])
                : "r"(a0), "r"(a1), "r"(a2), "r"(a3), "r"(bw.x), "r"(bw.y));
        }
    }

    // ---------------- Phase 3: +b2 (in acc) ; LN(64) ; GELU ; dot(W3)+b3 ---
    float s1a = 0.f, s2a = 0.f, s1b = 0.f, s2b = 0.f;
    #pragma unroll
    for (int nt = 0; nt < 8; ++nt) {
        #pragma unroll
        for (int j = 0; j < 2; ++j) {
            const float bb = b2s[nt * 8 + 2 * tig + j];
            acc[nt][j]     += bb;
            acc[nt][2 + j] += bb;
            const float tA = acc[nt][j];
            const float tB = acc[nt][2 + j];
            s1a += tA; s2a += tA * tA;
            s1b += tB; s2b += tB * tB;
        }
    }
    #pragma unroll
    for (int m = 1; m <= 2; m <<= 1) {
        s1a += __shfl_xor_sync(0xffffffffu, s1a, m);
        s2a += __shfl_xor_sync(0xffffffffu, s2a, m);
        s1b += __shfl_xor_sync(0xffffffffu, s1b, m);
        s2b += __shfl_xor_sync(0xffffffffu, s2b, m);
    }
    const float muA = s1a * (1.0f / HID2);
    const float rsA = rsqrtf(s2a * (1.0f / HID2) - muA * muA + 1e-5f);
    const float muB = s1b * (1.0f / HID2);
    const float rsB = rsqrtf(s2b * (1.0f / HID2) - muB * muB + 1e-5f);

    float dotA = 0.f, dotB = 0.f;
    #pragma unroll
    for (int nt = 0; nt < 8; ++nt) {
        #pragma unroll
        for (int j = 0; j < 2; ++j) {
            const int col = nt * 8 + 2 * tig + j;
            const float gg = g2s[col], be = be2s[col], ww = w3s[col];
            dotA = fmaf(gelu_fast((acc[nt][j]     - muA) * rsA * gg + be), ww, dotA);
            dotB = fmaf(gelu_fast((acc[nt][2 + j] - muB) * rsB * gg + be), ww, dotB);
        }
    }
    #pragma unroll
    for (int m = 1; m <= 2; m <<= 1) {
        dotA += __shfl_xor_sync(0xffffffffu, dotA, m);
        dotB += __shfl_xor_sync(0xffffffffu, dotB, m);
    }

    if (tig == 0) {
        const float b3v = b3[0];
        const int eA = e0 + r0 + gid;
        const int eB = eA + 8;
        if (eA < E) out[eA] = dotA + b3v;
        if (eB < E) out[eB] = dotB + b3v;
    }
}

// ---------------------------------------------------------------------------
extern "C" void kernel_launch(void* const* d_in, const int* in_sizes, int n_in,
                              void* d_out, int out_size)
{
    const float* drug = (const float*)d_in[0];
    const float* dis  = (const float*)d_in[1];
    const int*   src  = (const int*)  d_in[2];
    const int*   dst  = (const int*)  d_in[3];
    const float* W1   = (const float*)d_in[4];
    const float* b1   = (const float*)d_in[5];
    const float* g1   = (const float*)d_in[6];
    const float* be1  = (const float*)d_in[7];
    const float* W2   = (const float*)d_in[8];
    const float* b2   = (const float*)d_in[9];
    const float* g2   = (const float*)d_in[10];
    const float* be2  = (const float*)d_in[11];
    const float* W3   = (const float*)d_in[12];
    const float* b3   = (const float*)d_in[13];
    float* out = (float*)d_out;

    const int n_drug = in_sizes[0] / FEAT;
    const int n_dis  = in_sizes[1] / FEAT;
    const int E      = in_sizes[2];

    w2p_kernel<<<16, 256>>>(W2);

    const int nmax = n_drug > n_dis ? n_drug : n_dis;
    dim3 pgrid((nmax + 31) / 32, 2);
    precompute_kernel<<<pgrid, THREADS>>>(drug, dis, W1, n_drug, n_dis);

    cudaFuncSetAttribute(edge_kernel, cudaFuncAttributeMaxDynamicSharedMemorySize, SM_TOTAL);
    const int blocks = (E + BM - 1) / BM;
    edge_kernel<<<blocks, THREADS, SM_TOTAL>>>(
        src, dst, b1, g1, be1, b2, g2, be2, W3, b3, out, E);
}

// round 11
// speedup vs baseline: 1.7215x; 1.0031x over previous
#include <cuda_runtime.h>
#include <cuda_fp16.h>
#include <cstdint>

#define FEAT   128
#define HID    128
#define HID2   64
#define BM     128
#define THREADS 256
#define MAXN   10000
#define APITCH 136            // halves per row (272B) for the A tile

// smem layout (bytes)
#define SM_A    0                         // 128 x 136 fp16 = 34816
#define SM_BP   (128 * APITCH * 2)        // fragment-ready B: 16384
#define SM_PAR  (SM_BP + 16384)
#define SM_B1   SM_PAR
#define SM_G1   (SM_B1 + 512)
#define SM_BE1  (SM_G1 + 512)
#define SM_B2   (SM_BE1 + 512)
#define SM_G2   (SM_B2 + 256)
#define SM_BE2  (SM_G2 + 256)
#define SM_W3   (SM_BE2 + 256)
#define SM_TOTAL (SM_W3 + 256)            // 53760 B

__device__ __align__(16) float    g_Pdrug[MAXN * HID];
__device__ __align__(16) float    g_Pdis [MAXN * HID];
// B fragments in HMMA order: [(nt*8+kt)*32 + lane] -> uint2 {b0, b1}
__device__ __align__(16) uint32_t g_W2p[8 * 8 * 32 * 2];

__device__ __forceinline__ float gelu_fast(float x) {
    const float x2 = x * x;
    const float inner = x * fmaf(0.0356774081f, x2, 0.7978845608f);
    float t;
    asm("tanh.approx.f32 %0, %1;" : "=f"(t) : "f"(inner));
    return 0.5f * x * (1.0f + t);
}

// ---------------------------------------------------------------------------
__global__ void w2p_kernel(const float* __restrict__ W2) {
    const int i = blockIdx.x * blockDim.x + threadIdx.x;   // 0..4095
    if (i < 4096) {
        const int w    = i & 1;
        const int lane = (i >> 1) & 31;
        const int kt   = (i >> 6) & 7;
        const int nt   = i >> 9;
        const int gid  = lane >> 2, tig = lane & 3;
        const int n    = nt * 8 + gid;
        const int kb   = kt * 16 + (w ? 8 : 0) + 2 * tig;
        const __half h0 = __float2half_rn(W2[kb * HID2 + n]);
        const __half h1 = __float2half_rn(W2[(kb + 1) * HID2 + n]);
        uint32_t word = ((uint32_t)*(const uint16_t*)&h1 << 16) | *(const uint16_t*)&h0;
        g_W2p[((nt * 8 + kt) * 32 + lane) * 2 + w] = word;
    }
}

// ---------------------------------------------------------------------------
__global__ __launch_bounds__(THREADS) void precompute_kernel(
    const float* __restrict__ drug, const float* __restrict__ dis,
    const float* __restrict__ W1, int n_drug, int n_dis)
{
    const int table = blockIdx.y;
    const int n = table ? n_dis : n_drug;
    const float* __restrict__ feat = table ? dis : drug;
    const float* __restrict__ w    = W1 + (table ? (size_t)FEAT * HID : 0);
    float* __restrict__ outp       = table ? g_Pdis : g_Pdrug;

    const int n0 = blockIdx.x * 32;
    if (n0 >= n) return;

    __shared__ float fs[32][FEAT];
    const int tid = threadIdx.x;
    for (int idx = tid; idx < 32 * FEAT; idx += THREADS) {
        int node = idx >> 7, k = idx & 127;
        fs[node][k] = (n0 + node < n) ? feat[(size_t)(n0 + node) * FEAT + k] : 0.0f;
    }
    __syncthreads();

    const int tx = tid & 31, ty = tid >> 5;
    float acc[4][4] = {};
    #pragma unroll 4
    for (int k = 0; k < FEAT; ++k) {
        float wv[4];
        #pragma unroll
        for (int c = 0; c < 4; ++c) wv[c] = w[(size_t)k * HID + tx + 32 * c];
        #pragma unroll
        for (int i = 0; i < 4; ++i) {
            float f = fs[ty * 4 + i][k];
            #pragma unroll
            for (int c = 0; c < 4; ++c) acc[i][c] = fmaf(f, wv[c], acc[i][c]);
        }
    }
    #pragma unroll
    for (int i = 0; i < 4; ++i) {
        int node = n0 + ty * 4 + i;
        if (node < n) {
            #pragma unroll
            for (int c = 0; c < 4; ++c)
                outp[(size_t)node * HID + tx + 32 * c] = acc[i][c];
        }
    }
}

// ---------------------------------------------------------------------------
extern __shared__ char smem_raw[];

__global__ __launch_bounds__(THREADS, 4) void edge_kernel(
    const int* __restrict__ src, const int* __restrict__ dst,
    const float* __restrict__ b1, const float* __restrict__ g1, const float* __restrict__ be1,
    const float* __restrict__ b2, const float* __restrict__ g2, const float* __restrict__ be2,
    const float* __restrict__ W3, const float* __restrict__ b3,
    float* __restrict__ out, int E)
{
    __half* As   = (__half*)(smem_raw + SM_A);
    uint2*  Bp   = (uint2*)(smem_raw + SM_BP);
    float* b1s  = (float*)(smem_raw + SM_B1);
    float* g1s  = (float*)(smem_raw + SM_G1);
    float* be1s = (float*)(smem_raw + SM_BE1);
    float* b2s  = (float*)(smem_raw + SM_B2);
    float* g2s  = (float*)(smem_raw + SM_G2);
    float* be2s = (float*)(smem_raw + SM_BE2);
    float* w3s  = (float*)(smem_raw + SM_W3);

    const int tid = threadIdx.x;
    const int wid = tid >> 5, lane = tid & 31;
    const int e0 = blockIdx.x * BM;
    const int r0 = wid * 16;

    // Batched index load FIRST: its latency is absorbed by the smem fill +
    // barrier below. lanes 0-15: src, lanes 16-31: dst.
    int eidx = e0 + r0 + (lane & 15);
    if (eidx >= E) eidx = E - 1;                 // clamp (finite garbage ok)
    const int idx32 = (lane < 16) ? src[eidx] : dst[eidx];

    if (tid < HID)  { b1s[tid] = b1[tid]; g1s[tid] = g1[tid]; be1s[tid] = be1[tid]; }
    if (tid < HID2) { b2s[tid] = b2[tid]; g2s[tid] = g2[tid]; be2s[tid] = be2[tid]; w3s[tid] = W3[tid]; }

    // copy fragment-ready B (16 KB) with uint4 vectors
    {
        const uint4* __restrict__ w2v = (const uint4*)g_W2p;   // 1024 uint4
        #pragma unroll
        for (int i = tid; i < 1024; i += THREADS)
            ((uint4*)Bp)[i] = w2v[i];
    }
    __syncthreads();

    // ---------------- Phase 1: warp-local rows r0..r0+15, 4-row pipeline ---
    {
        const float4 bb = reinterpret_cast<const float4*>(b1s)[lane];
        const float4 gg = reinterpret_cast<const float4*>(g1s)[lane];
        const float4 ee = reinterpret_cast<const float4*>(be1s)[lane];

        #pragma unroll
        for (int i = 0; i < 16; i += 4) {
            float4 av[4], qv[4];
            #pragma unroll
            for (int r = 0; r < 4; ++r) {
                const int s = __shfl_sync(0xffffffffu, idx32, i + r);
                const int d = __shfl_sync(0xffffffffu, idx32, 16 + i + r);
                av[r] = reinterpret_cast<const float4*>(g_Pdrug + (size_t)s * HID)[lane];
                qv[r] = reinterpret_cast<const float4*>(g_Pdis  + (size_t)d * HID)[lane];
            }

            #pragma unroll
            for (int r = 0; r < 4; ++r) {
                float v[4];
                v[0] = av[r].x + qv[r].x + bb.x;
                v[1] = av[r].y + qv[r].y + bb.y;
                v[2] = av[r].z + qv[r].z + bb.z;
                v[3] = av[r].w + qv[r].w + bb.w;
                float s1r = v[0] + v[1] + v[2] + v[3];
                float s2r = v[0]*v[0] + v[1]*v[1] + v[2]*v[2] + v[3]*v[3];
                #pragma unroll
                for (int m = 16; m > 0; m >>= 1) {
                    s1r += __shfl_xor_sync(0xffffffffu, s1r, m);
                    s2r += __shfl_xor_sync(0xffffffffu, s2r, m);
                }
                const float mu  = s1r * (1.0f / HID);
                const float var = s2r * (1.0f / HID) - mu * mu;
                const float rs  = rsqrtf(var + 1e-5f);
                float h0 = gelu_fast((v[0] - mu) * rs * gg.x + ee.x);
                float h1 = gelu_fast((v[1] - mu) * rs * gg.y + ee.y);
                float h2 = gelu_fast((v[2] - mu) * rs * gg.z + ee.z);
                float h3 = gelu_fast((v[3] - mu) * rs * gg.w + ee.w);
                __half2 p0 = __floats2half2_rn(h0, h1);
                __half2 p1 = __floats2half2_rn(h2, h3);
                uint2 pk;
                pk.x = *reinterpret_cast<uint32_t*>(&p0);
                pk.y = *reinterpret_cast<uint32_t*>(&p1);
                *(uint2*)(As + (r0 + i + r) * APITCH + lane * 4) = pk;
            }
        }
    }
    __syncwarp();   // A rows are warp-private

    // ---------------- Phase 2: HMMA m16n8k16; A scalar LDS, B LDS.64 -------
    const int gid = lane >> 2, tig = lane & 3;

    float acc[8][4];
    #pragma unroll
    for (int nt = 0; nt < 8; ++nt)
        #pragma unroll
        for (int j = 0; j < 4; ++j) acc[nt][j] = 0.0f;

    #pragma unroll
    for (int kt = 0; kt < 8; ++kt) {
        const int k0 = kt * 16;
        const uint32_t* arow0 = (const uint32_t*)(As + (r0 + gid) * APITCH + k0);
        const uint32_t* arow8 = (const uint32_t*)(As + (r0 + gid + 8) * APITCH + k0);
        uint32_t a0 = arow0[tig];
        uint32_t a1 = arow8[tig];
        uint32_t a2 = arow0[tig + 4];
        uint32_t a3 = arow8[tig + 4];
        #pragma unroll
        for (int nt = 0; nt < 8; ++nt) {
            const uint2 bw = Bp[(nt * 8 + kt) * 32 + lane];
            asm volatile(
                "mma.sync.aligned.m16n8k16.row.col.f32.f16.f16.f32 "
                "{%0,%1,%2,%3}, {%4,%5,%6,%7}, {%8,%9}, {%0,%1,%2,%3};"
                : "+f"(acc[nt][0]), "+f"(acc[nt][1]), "+f"(acc[nt][2]), "+f"(acc[nt][3])
                : "r"(a0), "r"(a1), "r"(a2), "r"(a3), "r"(bw.x), "r"(bw.y));
        }
    }

    // ---------------- Phase 3: +b2 (in acc) ; LN(64) ; GELU ; dot(W3)+b3 ---
    float s1a = 0.f, s2a = 0.f, s1b = 0.f, s2b = 0.f;
    #pragma unroll
    for (int nt = 0; nt < 8; ++nt) {
        #pragma unroll
        for (int j = 0; j < 2; ++j) {
            const float bb = b2s[nt * 8 + 2 * tig + j];
            acc[nt][j]     += bb;
            acc[nt][2 + j] += bb;
            const float tA = acc[nt][j];
            const float tB = acc[nt][2 + j];
            s1a += tA; s2a += tA * tA;
            s1b += tB; s2b += tB * tB;
        }
    }
    #pragma unroll
    for (int m = 1; m <= 2; m <<= 1) {
        s1a += __shfl_xor_sync(0xffffffffu, s1a, m);
        s2a += __shfl_xor_sync(0xffffffffu, s2a, m);
        s1b += __shfl_xor_sync(0xffffffffu, s1b, m);
        s2b += __shfl_xor_sync(0xffffffffu, s2b, m);
    }
    const float muA = s1a * (1.0f / HID2);
    const float rsA = rsqrtf(s2a * (1.0f / HID2) - muA * muA + 1e-5f);
    const float muB = s1b * (1.0f / HID2);
    const float rsB = rsqrtf(s2b * (1.0f / HID2) - muB * muB + 1e-5f);

    float dotA = 0.f, dotB = 0.f;
    #pragma unroll
    for (int nt = 0; nt < 8; ++nt) {
        #pragma unroll
        for (int j = 0; j < 2; ++j) {
            const int col = nt * 8 + 2 * tig + j;
            const float gg = g2s[col], be = be2s[col], ww = w3s[col];
            dotA = fmaf(gelu_fast((acc[nt][j]     - muA) * rsA * gg + be), ww, dotA);
            dotB = fmaf(gelu_fast((acc[nt][2 + j] - muB) * rsB * gg + be), ww, dotB);
        }
    }
    #pragma unroll
    for (int m = 1; m <= 2; m <<= 1) {
        dotA += __shfl_xor_sync(0xffffffffu, dotA, m);
        dotB += __shfl_xor_sync(0xffffffffu, dotB, m);
    }

    if (tig == 0) {
        const float b3v = b3[0];
        const int eA = e0 + r0 + gid;
        const int eB = eA + 8;
        if (eA < E) out[eA] = dotA + b3v;
        if (eB < E) out[eB] = dotB + b3v;
    }
}

// ---------------------------------------------------------------------------
extern "C" void kernel_launch(void* const* d_in, const int* in_sizes, int n_in,
                              void* d_out, int out_size)
{
    const float* drug = (const float*)d_in[0];
    const float* dis  = (const float*)d_in[1];
    const int*   src  = (const int*)  d_in[2];
    const int*   dst  = (const int*)  d_in[3];
    const float* W1   = (const float*)d_in[4];
    const float* b1   = (const float*)d_in[5];
    const float* g1   = (const float*)d_in[6];
    const float* be1  = (const float*)d_in[7];
    const float* W2   = (const float*)d_in[8];
    const float* b2   = (const float*)d_in[9];
    const float* g2   = (const float*)d_in[10];
    const float* be2  = (const float*)d_in[11];
    const float* W3   = (const float*)d_in[12];
    const float* b3   = (const float*)d_in[13];
    float* out = (float*)d_out;

    const int n_drug = in_sizes[0] / FEAT;
    const int n_dis  = in_sizes[1] / FEAT;
    const int E      = in_sizes[2];

    w2p_kernel<<<16, 256>>>(W2);

    const int nmax = n_drug > n_dis ? n_drug : n_dis;
    dim3 pgrid((nmax + 31) / 32, 2);
    precompute_kernel<<<pgrid, THREADS>>>(drug, dis, W1, n_drug, n_dis);

    cudaFuncSetAttribute(edge_kernel, cudaFuncAttributeMaxDynamicSharedMemorySize, SM_TOTAL);
    const int blocks = (E + BM - 1) / BM;
    edge_kernel<<<blocks, THREADS, SM_TOTAL>>>(
        src, dst, b1, g1, be1, b2, g2, be2, W3, b3, out, E);
}

// round 12
// speedup vs baseline: 1.7791x; 1.0334x over previous
#include <cuda_runtime.h>
#include <cuda_fp16.h>
#include <cstdint>

#define FEAT   128
#define HID    128
#define HID2   64
#define BM     128
#define THREADS 256
#define MAXN   10000
#define APITCH 136            // halves per row (272B) for the A tile

// smem layout (bytes)
#define SM_A    0                         // 128 x 136 fp16 = 34816
#define SM_BP   (128 * APITCH * 2)        // fragment-ready B: 16384
#define SM_PAR  (SM_BP + 16384)
#define SM_B1   SM_PAR
#define SM_G1   (SM_B1 + 512)
#define SM_BE1  (SM_G1 + 512)
#define SM_B2   (SM_BE1 + 512)
#define SM_G2   (SM_B2 + 256)
#define SM_BE2  (SM_G2 + 256)
#define SM_W3   (SM_BE2 + 256)
#define SM_TOTAL (SM_W3 + 256)            // 53760 B

// fp16 per-node first-layer partials (L2-resident: 2 x 2.56 MB)
__device__ __align__(16) __half   g_PdrugH[MAXN * HID];
__device__ __align__(16) __half   g_PdisH [MAXN * HID];
// B fragments in HMMA order: [(nt*8+kt)*32 + lane] -> uint2 {b0, b1}
__device__ __align__(16) uint32_t g_W2p[8 * 8 * 32 * 2];

__device__ __forceinline__ float gelu_fast(float x) {
    const float x2 = x * x;
    const float inner = x * fmaf(0.0356774081f, x2, 0.7978845608f);
    float t;
    asm("tanh.approx.f32 %0, %1;" : "=f"(t) : "f"(inner));
    return 0.5f * x * (1.0f + t);
}

// ---------------------------------------------------------------------------
__global__ void w2p_kernel(const float* __restrict__ W2) {
    const int i = blockIdx.x * blockDim.x + threadIdx.x;   // 0..4095
    if (i < 4096) {
        const int w    = i & 1;
        const int lane = (i >> 1) & 31;
        const int kt   = (i >> 6) & 7;
        const int nt   = i >> 9;
        const int gid  = lane >> 2, tig = lane & 3;
        const int n    = nt * 8 + gid;
        const int kb   = kt * 16 + (w ? 8 : 0) + 2 * tig;
        const __half h0 = __float2half_rn(W2[kb * HID2 + n]);
        const __half h1 = __float2half_rn(W2[(kb + 1) * HID2 + n]);
        uint32_t word = ((uint32_t)*(const uint16_t*)&h1 << 16) | *(const uint16_t*)&h0;
        g_W2p[((nt * 8 + kt) * 32 + lane) * 2 + w] = word;
    }
}

// ---------------------------------------------------------------------------
__global__ __launch_bounds__(THREADS) void precompute_kernel(
    const float* __restrict__ drug, const float* __restrict__ dis,
    const float* __restrict__ W1, int n_drug, int n_dis)
{
    const int table = blockIdx.y;
    const int n = table ? n_dis : n_drug;
    const float* __restrict__ feat = table ? dis : drug;
    const float* __restrict__ w    = W1 + (table ? (size_t)FEAT * HID : 0);
    __half* __restrict__ outp      = table ? g_PdisH : g_PdrugH;

    const int n0 = blockIdx.x * 32;
    if (n0 >= n) return;

    __shared__ float fs[32][FEAT];
    const int tid = threadIdx.x;
    for (int idx = tid; idx < 32 * FEAT; idx += THREADS) {
        int node = idx >> 7, k = idx & 127;
        fs[node][k] = (n0 + node < n) ? feat[(size_t)(n0 + node) * FEAT + k] : 0.0f;
    }
    __syncthreads();

    const int tx = tid & 31, ty = tid >> 5;
    float acc[4][4] = {};
    #pragma unroll 4
    for (int k = 0; k < FEAT; ++k) {
        float wv[4];
        #pragma unroll
        for (int c = 0; c < 4; ++c) wv[c] = w[(size_t)k * HID + tx + 32 * c];
        #pragma unroll
        for (int i = 0; i < 4; ++i) {
            float f = fs[ty * 4 + i][k];
            #pragma unroll
            for (int c = 0; c < 4; ++c) acc[i][c] = fmaf(f, wv[c], acc[i][c]);
        }
    }
    #pragma unroll
    for (int i = 0; i < 4; ++i) {
        int node = n0 + ty * 4 + i;
        if (node < n) {
            #pragma unroll
            for (int c = 0; c < 4; ++c)
                outp[(size_t)node * HID + tx + 32 * c] = __float2half_rn(acc[i][c]);
        }
    }
}

// ---------------------------------------------------------------------------
extern __shared__ char smem_raw[];

__global__ __launch_bounds__(THREADS, 4) void edge_kernel(
    const int* __restrict__ src, const int* __restrict__ dst,
    const float* __restrict__ b1, const float* __restrict__ g1, const float* __restrict__ be1,
    const float* __restrict__ b2, const float* __restrict__ g2, const float* __restrict__ be2,
    const float* __restrict__ W3, const float* __restrict__ b3,
    float* __restrict__ out, int E)
{
    __half* As   = (__half*)(smem_raw + SM_A);
    uint2*  Bp   = (uint2*)(smem_raw + SM_BP);
    float* b1s  = (float*)(smem_raw + SM_B1);
    float* g1s  = (float*)(smem_raw + SM_G1);
    float* be1s = (float*)(smem_raw + SM_BE1);
    float* b2s  = (float*)(smem_raw + SM_B2);
    float* g2s  = (float*)(smem_raw + SM_G2);
    float* be2s = (float*)(smem_raw + SM_BE2);
    float* w3s  = (float*)(smem_raw + SM_W3);

    const int tid = threadIdx.x;
    const int wid = tid >> 5, lane = tid & 31;
    const int e0 = blockIdx.x * BM;
    const int r0 = wid * 16;

    // Batched index load FIRST; latency hidden behind smem fill + barrier.
    int eidx = e0 + r0 + (lane & 15);
    if (eidx >= E) eidx = E - 1;                 // clamp (finite garbage ok)
    const int idx32 = (lane < 16) ? src[eidx] : dst[eidx];

    if (tid < HID)  { b1s[tid] = b1[tid]; g1s[tid] = g1[tid]; be1s[tid] = be1[tid]; }
    if (tid < HID2) { b2s[tid] = b2[tid]; g2s[tid] = g2[tid]; be2s[tid] = be2[tid]; w3s[tid] = W3[tid]; }

    // copy fragment-ready B (16 KB) with uint4 vectors
    {
        const uint4* __restrict__ w2v = (const uint4*)g_W2p;   // 1024 uint4
        #pragma unroll
        for (int i = tid; i < 1024; i += THREADS)
            ((uint4*)Bp)[i] = w2v[i];
    }
    __syncthreads();

    // ---------------- Phase 1: warp-local rows r0..r0+15, 4-row pipeline ---
    {
        const float4 bb = reinterpret_cast<const float4*>(b1s)[lane];
        const float4 gg = reinterpret_cast<const float4*>(g1s)[lane];
        const float4 ee = reinterpret_cast<const float4*>(be1s)[lane];

        #pragma unroll
        for (int i = 0; i < 16; i += 4) {
            uint2 ap[4], qp[4];
            #pragma unroll
            for (int r = 0; r < 4; ++r) {
                const int s = __shfl_sync(0xffffffffu, idx32, i + r);
                const int d = __shfl_sync(0xffffffffu, idx32, 16 + i + r);
                ap[r] = *(const uint2*)(g_PdrugH + (size_t)s * HID + lane * 4);
                qp[r] = *(const uint2*)(g_PdisH  + (size_t)d * HID + lane * 4);
            }

            #pragma unroll
            for (int r = 0; r < 4; ++r) {
                const float2 a01 = __half22float2(*(const __half2*)&ap[r].x);
                const float2 a23 = __half22float2(*(const __half2*)&ap[r].y);
                const float2 q01 = __half22float2(*(const __half2*)&qp[r].x);
                const float2 q23 = __half22float2(*(const __half2*)&qp[r].y);
                float v[4];
                v[0] = a01.x + q01.x + bb.x;
                v[1] = a01.y + q01.y + bb.y;
                v[2] = a23.x + q23.x + bb.z;
                v[3] = a23.y + q23.y + bb.w;
                float s1r = v[0] + v[1] + v[2] + v[3];
                float s2r = v[0]*v[0] + v[1]*v[1] + v[2]*v[2] + v[3]*v[3];
                #pragma unroll
                for (int m = 16; m > 0; m >>= 1) {
                    s1r += __shfl_xor_sync(0xffffffffu, s1r, m);
                    s2r += __shfl_xor_sync(0xffffffffu, s2r, m);
                }
                const float mu  = s1r * (1.0f / HID);
                const float var = s2r * (1.0f / HID) - mu * mu;
                const float rs  = rsqrtf(var + 1e-5f);
                float h0 = gelu_fast((v[0] - mu) * rs * gg.x + ee.x);
                float h1 = gelu_fast((v[1] - mu) * rs * gg.y + ee.y);
                float h2 = gelu_fast((v[2] - mu) * rs * gg.z + ee.z);
                float h3 = gelu_fast((v[3] - mu) * rs * gg.w + ee.w);
                __half2 p0 = __floats2half2_rn(h0, h1);
                __half2 p1 = __floats2half2_rn(h2, h3);
                uint2 pk;
                pk.x = *reinterpret_cast<uint32_t*>(&p0);
                pk.y = *reinterpret_cast<uint32_t*>(&p1);
                *(uint2*)(As + (r0 + i + r) * APITCH + lane * 4) = pk;
            }
        }
    }
    __syncwarp();   // A rows are warp-private

    // ---------------- Phase 2: HMMA m16n8k16; A scalar LDS, B LDS.64 -------
    const int gid = lane >> 2, tig = lane & 3;

    float acc[8][4];
    #pragma unroll
    for (int nt = 0; nt < 8; ++nt)
        #pragma unroll
        for (int j = 0; j < 4; ++j) acc[nt][j] = 0.0f;

    #pragma unroll
    for (int kt = 0; kt < 8; ++kt) {
        const int k0 = kt * 16;
        const uint32_t* arow0 = (const uint32_t*)(As + (r0 + gid) * APITCH + k0);
        const uint32_t* arow8 = (const uint32_t*)(As + (r0 + gid + 8) * APITCH + k0);
        uint32_t a0 = arow0[tig];
        uint32_t a1 = arow8[tig];
        uint32_t a2 = arow0[tig + 4];
        uint32_t a3 = arow8[tig + 4];
        #pragma unroll
        for (int nt = 0; nt < 8; ++nt) {
            const uint2 bw = Bp[(nt * 8 + kt) * 32 + lane];
            asm volatile(
                "mma.sync.aligned.m16n8k16.row.col.f32.f16.f16.f32 "
                "{%0,%1,%2,%3}, {%4,%5,%6,%7}, {%8,%9}, {%0,%1,%2,%3};"
                : "+f"(acc[nt][0]), "+f"(acc[nt][1]), "+f"(acc[nt][2]), "+f"(acc[nt][3])
                : "r"(a0), "r"(a1), "r"(a2), "r"(a3), "r"(bw.x), "r"(bw.y));
        }
    }

    // ---------------- Phase 3: +b2 (in acc) ; LN(64) ; GELU ; dot(W3)+b3 ---
    float s1a = 0.f, s2a = 0.f, s1b = 0.f, s2b = 0.f;
    #pragma unroll
    for (int nt = 0; nt < 8; ++nt) {
        #pragma unroll
        for (int j = 0; j < 2; ++j) {
            const float bb = b2s[nt * 8 + 2 * tig + j];
            acc[nt][j]     += bb;
            acc[nt][2 + j] += bb;
            const float tA = acc[nt][j];
            const float tB = acc[nt][2 + j];
            s1a += tA; s2a += tA * tA;
            s1b += tB; s2b += tB * tB;
        }
    }
    #pragma unroll
    for (int m = 1; m <= 2; m <<= 1) {
        s1a += __shfl_xor_sync(0xffffffffu, s1a, m);
        s2a += __shfl_xor_sync(0xffffffffu, s2a, m);
        s1b += __shfl_xor_sync(0xffffffffu, s1b, m);
        s2b += __shfl_xor_sync(0xffffffffu, s2b, m);
    }
    const float muA = s1a * (1.0f / HID2);
    const float rsA = rsqrtf(s2a * (1.0f / HID2) - muA * muA + 1e-5f);
    const float muB = s1b * (1.0f / HID2);
    const float rsB = rsqrtf(s2b * (1.0f / HID2) - muB * muB + 1e-5f);

    float dotA = 0.f, dotB = 0.f;
    #pragma unroll
    for (int nt = 0; nt < 8; ++nt) {
        #pragma unroll
        for (int j = 0; j < 2; ++j) {
            const int col = nt * 8 + 2 * tig + j;
            const float gg = g2s[col], be = be2s[col], ww = w3s[col];
            dotA = fmaf(gelu_fast((acc[nt][j]     - muA) * rsA * gg + be), ww, dotA);
            dotB = fmaf(gelu_fast((acc[nt][2 + j] - muB) * rsB * gg + be), ww, dotB);
        }
    }
    #pragma unroll
    for (int m = 1; m <= 2; m <<= 1) {
        dotA += __shfl_xor_sync(0xffffffffu, dotA, m);
        dotB += __shfl_xor_sync(0xffffffffu, dotB, m);
    }

    if (tig == 0) {
        const float b3v = b3[0];
        const int eA = e0 + r0 + gid;
        const int eB = eA + 8;
        if (eA < E) out[eA] = dotA + b3v;
        if (eB < E) out[eB] = dotB + b3v;
    }
}

// ---------------------------------------------------------------------------
extern "C" void kernel_launch(void* const* d_in, const int* in_sizes, int n_in,
                              void* d_out, int out_size)
{
    const float* drug = (const float*)d_in[0];
    const float* dis  = (const float*)d_in[1];
    const int*   src  = (const int*)  d_in[2];
    const int*   dst  = (const int*)  d_in[3];
    const float* W1   = (const float*)d_in[4];
    const float* b1   = (const float*)d_in[5];
    const float* g1   = (const float*)d_in[6];
    const float* be1  = (const float*)d_in[7];
    const float* W2   = (const float*)d_in[8];
    const float* b2   = (const float*)d_in[9];
    const float* g2   = (const float*)d_in[10];
    const float* be2  = (const float*)d_in[11];
    const float* W3   = (const float*)d_in[12];
    const float* b3   = (const float*)d_in[13];
    float* out = (float*)d_out;

    const int n_drug = in_sizes[0] / FEAT;
    const int n_dis  = in_sizes[1] / FEAT;
    const int E      = in_sizes[2];

    w2p_kernel<<<16, 256>>>(W2);

    const int nmax = n_drug > n_dis ? n_drug : n_dis;
    dim3 pgrid((nmax + 31) / 32, 2);
    precompute_kernel<<<pgrid, THREADS>>>(drug, dis, W1, n_drug, n_dis);

    cudaFuncSetAttribute(edge_kernel, cudaFuncAttributeMaxDynamicSharedMemorySize, SM_TOTAL);
    const int blocks = (E + BM - 1) / BM;
    edge_kernel<<<blocks, THREADS, SM_TOTAL>>>(
        src, dst, b1, g1, be1, b2, g2, be2, W3, b3, out, E);
}

// round 13
// speedup vs baseline: 1.7924x; 1.0075x over previous
#include <cuda_runtime.h>
#include <cuda_fp16.h>
#include <cstdint>

#define FEAT   128
#define HID    128
#define HID2   64
#define BM     128
#define THREADS 256
#define MAXN   10000
#define APITCH 136            // halves per row (272B) for the A tile

// smem layout (bytes)
#define SM_A    0                         // 128 x 136 fp16 = 34816
#define SM_BP   (128 * APITCH * 2)        // fragment-ready B: 16384
#define SM_PAR  (SM_BP + 16384)
#define SM_B1   SM_PAR
#define SM_G1   (SM_B1 + 512)
#define SM_BE1  (SM_G1 + 512)
#define SM_B2   (SM_BE1 + 512)
#define SM_G2   (SM_B2 + 256)
#define SM_BE2  (SM_G2 + 256)
#define SM_W3   (SM_BE2 + 256)
#define SM_TOTAL (SM_W3 + 256)            // 53760 B

// fp16 per-node first-layer partials (L2-resident: 2 x 2.56 MB)
__device__ __align__(16) __half   g_PdrugH[MAXN * HID];
__device__ __align__(16) __half   g_PdisH [MAXN * HID];
// B fragments in HMMA order: [(nt*8+kt)*32 + lane] -> uint2 {b0, b1}
__device__ __align__(16) uint32_t g_W2p[8 * 8 * 32 * 2];

__device__ __forceinline__ float gelu_fast(float x) {
    const float x2 = x * x;
    const float inner = x * fmaf(0.0356774081f, x2, 0.7978845608f);
    float t;
    asm("tanh.approx.f32 %0, %1;" : "=f"(t) : "f"(inner));
    return 0.5f * x * (1.0f + t);
}

// ---------------------------------------------------------------------------
__global__ void w2p_kernel(const float* __restrict__ W2) {
    const int i = blockIdx.x * blockDim.x + threadIdx.x;   // 0..4095
    if (i < 4096) {
        const int w    = i & 1;
        const int lane = (i >> 1) & 31;
        const int kt   = (i >> 6) & 7;
        const int nt   = i >> 9;
        const int gid  = lane >> 2, tig = lane & 3;
        const int n    = nt * 8 + gid;
        const int kb   = kt * 16 + (w ? 8 : 0) + 2 * tig;
        const __half h0 = __float2half_rn(W2[kb * HID2 + n]);
        const __half h1 = __float2half_rn(W2[(kb + 1) * HID2 + n]);
        uint32_t word = ((uint32_t)*(const uint16_t*)&h1 << 16) | *(const uint16_t*)&h0;
        g_W2p[((nt * 8 + kt) * 32 + lane) * 2 + w] = word;
    }
}

// ---------------------------------------------------------------------------
__global__ __launch_bounds__(THREADS) void precompute_kernel(
    const float* __restrict__ drug, const float* __restrict__ dis,
    const float* __restrict__ W1, int n_drug, int n_dis)
{
    const int table = blockIdx.y;
    const int n = table ? n_dis : n_drug;
    const float* __restrict__ feat = table ? dis : drug;
    const float* __restrict__ w    = W1 + (table ? (size_t)FEAT * HID : 0);
    __half* __restrict__ outp      = table ? g_PdisH : g_PdrugH;

    const int n0 = blockIdx.x * 32;
    if (n0 >= n) return;

    __shared__ float fs[32][FEAT];
    const int tid = threadIdx.x;
    for (int idx = tid; idx < 32 * FEAT; idx += THREADS) {
        int node = idx >> 7, k = idx & 127;
        fs[node][k] = (n0 + node < n) ? feat[(size_t)(n0 + node) * FEAT + k] : 0.0f;
    }
    __syncthreads();

    const int tx = tid & 31, ty = tid >> 5;
    float acc[4][4] = {};
    #pragma unroll 4
    for (int k = 0; k < FEAT; ++k) {
        float wv[4];
        #pragma unroll
        for (int c = 0; c < 4; ++c) wv[c] = w[(size_t)k * HID + tx + 32 * c];
        #pragma unroll
        for (int i = 0; i < 4; ++i) {
            float f = fs[ty * 4 + i][k];
            #pragma unroll
            for (int c = 0; c < 4; ++c) acc[i][c] = fmaf(f, wv[c], acc[i][c]);
        }
    }
    #pragma unroll
    for (int i = 0; i < 4; ++i) {
        int node = n0 + ty * 4 + i;
        if (node < n) {
            #pragma unroll
            for (int c = 0; c < 4; ++c)
                outp[(size_t)node * HID + tx + 32 * c] = __float2half_rn(acc[i][c]);
        }
    }
}

// ---------------------------------------------------------------------------
extern __shared__ char smem_raw[];

__global__ __launch_bounds__(THREADS, 4) void edge_kernel(
    const int* __restrict__ src, const int* __restrict__ dst,
    const float* __restrict__ b1, const float* __restrict__ g1, const float* __restrict__ be1,
    const float* __restrict__ b2, const float* __restrict__ g2, const float* __restrict__ be2,
    const float* __restrict__ W3, const float* __restrict__ b3,
    float* __restrict__ out, int E)
{
    __half* As   = (__half*)(smem_raw + SM_A);
    uint2*  Bp   = (uint2*)(smem_raw + SM_BP);
    float* b1s  = (float*)(smem_raw + SM_B1);
    float* g1s  = (float*)(smem_raw + SM_G1);
    float* be1s = (float*)(smem_raw + SM_BE1);
    float* b2s  = (float*)(smem_raw + SM_B2);
    float* g2s  = (float*)(smem_raw + SM_G2);
    float* be2s = (float*)(smem_raw + SM_BE2);
    float* w3s  = (float*)(smem_raw + SM_W3);

    const int tid = threadIdx.x;
    const int wid = tid >> 5, lane = tid & 31;
    const int e0 = blockIdx.x * BM;
    const int r0 = wid * 16;

    // Batched index load FIRST; latency hidden behind smem fill + barrier.
    int eidx = e0 + r0 + (lane & 15);
    if (eidx >= E) eidx = E - 1;                 // clamp (finite garbage ok)
    const int idx32 = (lane < 16) ? src[eidx] : dst[eidx];

    if (tid < HID)  { b1s[tid] = b1[tid]; g1s[tid] = g1[tid]; be1s[tid] = be1[tid]; }
    if (tid < HID2) { b2s[tid] = b2[tid]; g2s[tid] = g2[tid]; be2s[tid] = be2[tid]; w3s[tid] = W3[tid]; }

    // copy fragment-ready B (16 KB) with uint4 vectors
    {
        const uint4* __restrict__ w2v = (const uint4*)g_W2p;   // 1024 uint4
        #pragma unroll
        for (int i = tid; i < 1024; i += THREADS)
            ((uint4*)Bp)[i] = w2v[i];
    }
    __syncthreads();

    // ---------------- Phase 1: warp-local rows, cross-batch prefetch -------
    {
        const float4 bb = reinterpret_cast<const float4*>(b1s)[lane];
        const float4 gg = reinterpret_cast<const float4*>(g1s)[lane];
        const float4 ee = reinterpret_cast<const float4*>(be1s)[lane];

        uint2 ap[2][4], qp[2][4];
        // prologue: batch 0 gathers
        #pragma unroll
        for (int r = 0; r < 4; ++r) {
            const int s = __shfl_sync(0xffffffffu, idx32, r);
            const int d = __shfl_sync(0xffffffffu, idx32, 16 + r);
            ap[0][r] = *(const uint2*)(g_PdrugH + (size_t)s * HID + lane * 4);
            qp[0][r] = *(const uint2*)(g_PdisH  + (size_t)d * HID + lane * 4);
        }

        #pragma unroll
        for (int ib = 0; ib < 4; ++ib) {
            const int cur = ib & 1, nxt = cur ^ 1;
            // issue NEXT batch's gathers before consuming this one
            if (ib < 3) {
                #pragma unroll
                for (int r = 0; r < 4; ++r) {
                    const int s = __shfl_sync(0xffffffffu, idx32, (ib + 1) * 4 + r);
                    const int d = __shfl_sync(0xffffffffu, idx32, 16 + (ib + 1) * 4 + r);
                    ap[nxt][r] = *(const uint2*)(g_PdrugH + (size_t)s * HID + lane * 4);
                    qp[nxt][r] = *(const uint2*)(g_PdisH  + (size_t)d * HID + lane * 4);
                }
            }
            #pragma unroll
            for (int r = 0; r < 4; ++r) {
                const float2 a01 = __half22float2(*(const __half2*)&ap[cur][r].x);
                const float2 a23 = __half22float2(*(const __half2*)&ap[cur][r].y);
                const float2 q01 = __half22float2(*(const __half2*)&qp[cur][r].x);
                const float2 q23 = __half22float2(*(const __half2*)&qp[cur][r].y);
                float v[4];
                v[0] = a01.x + q01.x + bb.x;
                v[1] = a01.y + q01.y + bb.y;
                v[2] = a23.x + q23.x + bb.z;
                v[3] = a23.y + q23.y + bb.w;
                float s1r = v[0] + v[1] + v[2] + v[3];
                float s2r = v[0]*v[0] + v[1]*v[1] + v[2]*v[2] + v[3]*v[3];
                #pragma unroll
                for (int m = 16; m > 0; m >>= 1) {
                    s1r += __shfl_xor_sync(0xffffffffu, s1r, m);
                    s2r += __shfl_xor_sync(0xffffffffu, s2r, m);
                }
                const float mu  = s1r * (1.0f / HID);
                const float var = s2r * (1.0f / HID) - mu * mu;
                const float rs  = rsqrtf(var + 1e-5f);
                float h0 = gelu_fast((v[0] - mu) * rs * gg.x + ee.x);
                float h1 = gelu_fast((v[1] - mu) * rs * gg.y + ee.y);
                float h2 = gelu_fast((v[2] - mu) * rs * gg.z + ee.z);
                float h3 = gelu_fast((v[3] - mu) * rs * gg.w + ee.w);
                __half2 p0 = __floats2half2_rn(h0, h1);
                __half2 p1 = __floats2half2_rn(h2, h3);
                uint2 pk;
                pk.x = *reinterpret_cast<uint32_t*>(&p0);
                pk.y = *reinterpret_cast<uint32_t*>(&p1);
                *(uint2*)(As + (r0 + ib * 4 + r) * APITCH + lane * 4) = pk;
            }
        }
    }
    __syncwarp();   // A rows are warp-private

    // ---------------- Phase 2: HMMA m16n8k16; A scalar LDS, B LDS.64 -------
    const int gid = lane >> 2, tig = lane & 3;

    float acc[8][4];
    #pragma unroll
    for (int nt = 0; nt < 8; ++nt)
        #pragma unroll
        for (int j = 0; j < 4; ++j) acc[nt][j] = 0.0f;

    #pragma unroll
    for (int kt = 0; kt < 8; ++kt) {
        const int k0 = kt * 16;
        const uint32_t* arow0 = (const uint32_t*)(As + (r0 + gid) * APITCH + k0);
        const uint32_t* arow8 = (const uint32_t*)(As + (r0 + gid + 8) * APITCH + k0);
        uint32_t a0 = arow0[tig];
        uint32_t a1 = arow8[tig];
        uint32_t a2 = arow0[tig + 4];
        uint32_t a3 = arow8[tig + 4];
        #pragma unroll
        for (int nt = 0; nt < 8; ++nt) {
            const uint2 bw = Bp[(nt * 8 + kt) * 32 + lane];
            asm volatile(
                "mma.sync.aligned.m16n8k16.row.col.f32.f16.f16.f32 "
                "{%0,%1,%2,%3}, {%4,%5,%6,%7}, {%8,%9}, {%0,%1,%2,%3};"
                : "+f"(acc[nt][0]), "+f"(acc[nt][1]), "+f"(acc[nt][2]), "+f"(acc[nt][3])
                : "r"(a0), "r"(a1), "r"(a2), "r"(a3), "r"(bw.x), "r"(bw.y));
        }
    }

    // ---------------- Phase 3: +b2 (in acc) ; LN(64) ; GELU ; dot(W3)+b3 ---
    float s1a = 0.f, s2a = 0.f, s1b = 0.f, s2b = 0.f;
    #pragma unroll
    for (int nt = 0; nt < 8; ++nt) {
        #pragma unroll
        for (int j = 0; j < 2; ++j) {
            const float bb = b2s[nt * 8 + 2 * tig + j];
            acc[nt][j]     += bb;
            acc[nt][2 + j] += bb;
            const float tA = acc[nt][j];
            const float tB = acc[nt][2 + j];
            s1a += tA; s2a += tA * tA;
            s1b += tB; s2b += tB * tB;
        }
    }
    #pragma unroll
    for (int m = 1; m <= 2; m <<= 1) {
        s1a += __shfl_xor_sync(0xffffffffu, s1a, m);
        s2a += __shfl_xor_sync(0xffffffffu, s2a, m);
        s1b += __shfl_xor_sync(0xffffffffu, s1b, m);
        s2b += __shfl_xor_sync(0xffffffffu, s2b, m);
    }
    const float muA = s1a * (1.0f / HID2);
    const float rsA = rsqrtf(s2a * (1.0f / HID2) - muA * muA + 1e-5f);
    const float muB = s1b * (1.0f / HID2);
    const float rsB = rsqrtf(s2b * (1.0f / HID2) - muB * muB + 1e-5f);

    float dotA = 0.f, dotB = 0.f;
    #pragma unroll
    for (int nt = 0; nt < 8; ++nt) {
        #pragma unroll
        for (int j = 0; j < 2; ++j) {
            const int col = nt * 8 + 2 * tig + j;
            const float gg = g2s[col], be = be2s[col], ww = w3s[col];
            dotA = fmaf(gelu_fast((acc[nt][j]     - muA) * rsA * gg + be), ww, dotA);
            dotB = fmaf(gelu_fast((acc[nt][2 + j] - muB) * rsB * gg + be), ww, dotB);
        }
    }
    #pragma unroll
    for (int m = 1; m <= 2; m <<= 1) {
        dotA += __shfl_xor_sync(0xffffffffu, dotA, m);
        dotB += __shfl_xor_sync(0xffffffffu, dotB, m);
    }

    if (tig == 0) {
        const float b3v = b3[0];
        const int eA = e0 + r0 + gid;
        const int eB = eA + 8;
        if (eA < E) out[eA] = dotA + b3v;
        if (eB < E) out[eB] = dotB + b3v;
    }
}

// ---------------------------------------------------------------------------
extern "C" void kernel_launch(void* const* d_in, const int* in_sizes, int n_in,
                              void* d_out, int out_size)
{
    const float* drug = (const float*)d_in[0];
    const float* dis  = (const float*)d_in[1];
    const int*   src  = (const int*)  d_in[2];
    const int*   dst  = (const int*)  d_in[3];
    const float* W1   = (const float*)d_in[4];
    const float* b1   = (const float*)d_in[5];
    const float* g1   = (const float*)d_in[6];
    const float* be1  = (const float*)d_in[7];
    const float* W2   = (const float*)d_in[8];
    const float* b2   = (const float*)d_in[9];
    const float* g2   = (const float*)d_in[10];
    const float* be2  = (const float*)d_in[11];
    const float* W3   = (const float*)d_in[12];
    const float* b3   = (const float*)d_in[13];
    float* out = (float*)d_out;

    const int n_drug = in_sizes[0] / FEAT;
    const int n_dis  = in_sizes[1] / FEAT;
    const int E      = in_sizes[2];

    w2p_kernel<<<16, 256>>>(W2);

    const int nmax = n_drug > n_dis ? n_drug : n_dis;
    dim3 pgrid((nmax + 31) / 32, 2);
    precompute_kernel<<<pgrid, THREADS>>>(drug, dis, W1, n_drug, n_dis);

    cudaFuncSetAttribute(edge_kernel, cudaFuncAttributeMaxDynamicSharedMemorySize, SM_TOTAL);
    const int blocks = (E + BM - 1) / BM;
    edge_kernel<<<blocks, THREADS, SM_TOTAL>>>(
        src, dst, b1, g1, be1, b2, g2, be2, W3, b3, out, E);
}

// round 14
// speedup vs baseline: 1.8486x; 1.0314x over previous
#include <cuda_runtime.h>
#include <cuda_fp16.h>
#include <cstdint>

#define FEAT   128
#define HID    128
#define HID2   64
#define BM     128
#define THREADS 256
#define MAXN   10000
#define APITCH 136            // halves per row (272B) for the A tile

// smem layout (bytes)
#define SM_A    0                         // 128 x 136 fp16 = 34816
#define SM_BP   (128 * APITCH * 2)        // fragment-ready B: 16384
#define SM_G1   (SM_BP + 16384)
#define SM_BE1  (SM_G1 + 512)
#define SM_B2   (SM_BE1 + 512)
#define SM_G2   (SM_B2 + 256)
#define SM_BE2  (SM_G2 + 256)
#define SM_W3   (SM_BE2 + 256)
#define SM_TOTAL (SM_W3 + 256)            // 53248 B

// fp16 per-node first-layer partials (drug table has b1 folded in)
__device__ __align__(16) __half   g_PdrugH[MAXN * HID];
__device__ __align__(16) __half   g_PdisH [MAXN * HID];
// per-node sums of the fp16 table rows (for analytic LN mean)
__device__ float g_Sdrug[MAXN];
__device__ float g_Sdis [MAXN];
// B fragments in HMMA order: [(nt*8+kt)*32 + lane] -> uint2 {b0, b1}
__device__ __align__(16) uint32_t g_W2p[8 * 8 * 32 * 2];

__device__ __forceinline__ float gelu_fast(float x) {
    const float x2 = x * x;
    const float inner = x * fmaf(0.0356774081f, x2, 0.7978845608f);
    float t;
    asm("tanh.approx.f32 %0, %1;" : "=f"(t) : "f"(inner));
    return 0.5f * x * (1.0f + t);
}

// ---------------------------------------------------------------------------
// Fused precompute: per-node P tables (+b1 fold for drug), per-node sums,
// and (last block) the W2 fragment permute.
// ---------------------------------------------------------------------------
__global__ __launch_bounds__(THREADS) void precompute_kernel(
    const float* __restrict__ drug, const float* __restrict__ dis,
    const float* __restrict__ W1, const float* __restrict__ b1,
    const float* __restrict__ W2, int n_drug, int n_dis)
{
    // Last block row 0: W2 -> fragment-ready fp16 permute
    if (blockIdx.x == gridDim.x - 1) {
        if (blockIdx.y == 0) {
            for (int i = threadIdx.x; i < 4096; i += THREADS) {
                const int w    = i & 1;
                const int lane = (i >> 1) & 31;
                const int kt   = (i >> 6) & 7;
                const int nt   = i >> 9;
                const int gid  = lane >> 2, tig = lane & 3;
                const int n    = nt * 8 + gid;
                const int kb   = kt * 16 + (w ? 8 : 0) + 2 * tig;
                const __half h0 = __float2half_rn(W2[kb * HID2 + n]);
                const __half h1 = __float2half_rn(W2[(kb + 1) * HID2 + n]);
                uint32_t word = ((uint32_t)*(const uint16_t*)&h1 << 16) | *(const uint16_t*)&h0;
                g_W2p[((nt * 8 + kt) * 32 + lane) * 2 + w] = word;
            }
        }
        return;
    }

    const int table = blockIdx.y;
    const int n = table ? n_dis : n_drug;
    const float* __restrict__ feat = table ? dis : drug;
    const float* __restrict__ w    = W1 + (table ? (size_t)FEAT * HID : 0);
    __half* __restrict__ outp      = table ? g_PdisH : g_PdrugH;
    float*  __restrict__ sump      = table ? g_Sdis  : g_Sdrug;

    const int n0 = blockIdx.x * 32;
    if (n0 >= n) return;

    __shared__ float fs[32][FEAT];
    const int tid = threadIdx.x;
    for (int idx = tid; idx < 32 * FEAT; idx += THREADS) {
        int node = idx >> 7, k = idx & 127;
        fs[node][k] = (n0 + node < n) ? feat[(size_t)(n0 + node) * FEAT + k] : 0.0f;
    }
    __syncthreads();

    const int tx = tid & 31, ty = tid >> 5;
    float acc[4][4] = {};
    #pragma unroll 4
    for (int k = 0; k < FEAT; ++k) {
        float wv[4];
        #pragma unroll
        for (int c = 0; c < 4; ++c) wv[c] = w[(size_t)k * HID + tx + 32 * c];
        #pragma unroll
        for (int i = 0; i < 4; ++i) {
            float f = fs[ty * 4 + i][k];
            #pragma unroll
            for (int c = 0; c < 4; ++c) acc[i][c] = fmaf(f, wv[c], acc[i][c]);
        }
    }
    // fold b1 into the drug table
    if (table == 0) {
        #pragma unroll
        for (int i = 0; i < 4; ++i)
            #pragma unroll
            for (int c = 0; c < 4; ++c) acc[i][c] += b1[tx + 32 * c];
    }
    #pragma unroll
    for (int i = 0; i < 4; ++i) {
        const int node = n0 + ty * 4 + i;
        // fp16-round, store, and accumulate the row sum of the ROUNDED values
        float loc = 0.0f;
        #pragma unroll
        for (int c = 0; c < 4; ++c) {
            const __half h = __float2half_rn(acc[i][c]);
            if (node < n) outp[(size_t)node * HID + tx + 32 * c] = h;
            loc += __half2float(h);
        }
        #pragma unroll
        for (int m = 16; m > 0; m >>= 1)
            loc += __shfl_xor_sync(0xffffffffu, loc, m);
        if (tx == 0 && node < n) sump[node] = loc;
    }
}

// ---------------------------------------------------------------------------
extern __shared__ char smem_raw[];

__global__ __launch_bounds__(THREADS, 4) void edge_kernel(
    const int* __restrict__ src, const int* __restrict__ dst,
    const float* __restrict__ g1, const float* __restrict__ be1,
    const float* __restrict__ b2, const float* __restrict__ g2, const float* __restrict__ be2,
    const float* __restrict__ W3, const float* __restrict__ b3,
    float* __restrict__ out, int E)
{
    __half* As   = (__half*)(smem_raw + SM_A);
    uint2*  Bp   = (uint2*)(smem_raw + SM_BP);
    float* g1s  = (float*)(smem_raw + SM_G1);
    float* be1s = (float*)(smem_raw + SM_BE1);
    float* b2s  = (float*)(smem_raw + SM_B2);
    float* g2s  = (float*)(smem_raw + SM_G2);
    float* be2s = (float*)(smem_raw + SM_BE2);
    float* w3s  = (float*)(smem_raw + SM_W3);

    const int tid = threadIdx.x;
    const int wid = tid >> 5, lane = tid & 31;
    const int e0 = blockIdx.x * BM;
    const int r0 = wid * 16;

    // Batched index load FIRST; latency hidden behind smem fill + barrier.
    int eidx = e0 + r0 + (lane & 15);
    if (eidx >= E) eidx = E - 1;                 // clamp (finite garbage ok)
    const int idx32 = (lane < 16) ? src[eidx] : dst[eidx];

    if (tid < HID)  { g1s[tid] = g1[tid]; be1s[tid] = be1[tid]; }
    if (tid < HID2) { b2s[tid] = b2[tid]; g2s[tid] = g2[tid]; be2s[tid] = be2[tid]; w3s[tid] = W3[tid]; }

    // copy fragment-ready B (16 KB) with uint4 vectors
    {
        const uint4* __restrict__ w2v = (const uint4*)g_W2p;   // 1024 uint4
        #pragma unroll
        for (int i = tid; i < 1024; i += THREADS)
            ((uint4*)Bp)[i] = w2v[i];
    }
    __syncthreads();

    // ---------------- Phase 1: warp-local rows, prefetch + analytic mean ---
    {
        const float4 gg = reinterpret_cast<const float4*>(g1s)[lane];
        const float4 ee = reinterpret_cast<const float4*>(be1s)[lane];

        uint2 ap[2][4], qp[2][4];
        float sv[2][4];
        // prologue: batch 0
        #pragma unroll
        for (int r = 0; r < 4; ++r) {
            const int s = __shfl_sync(0xffffffffu, idx32, r);
            const int d = __shfl_sync(0xffffffffu, idx32, 16 + r);
            ap[0][r] = *(const uint2*)(g_PdrugH + (size_t)s * HID + lane * 4);
            qp[0][r] = *(const uint2*)(g_PdisH  + (size_t)d * HID + lane * 4);
            sv[0][r] = g_Sdrug[s] + g_Sdis[d];
        }

        #pragma unroll
        for (int ib = 0; ib < 4; ++ib) {
            const int cur = ib & 1, nxt = cur ^ 1;
            if (ib < 3) {
                #pragma unroll
                for (int r = 0; r < 4; ++r) {
                    const int s = __shfl_sync(0xffffffffu, idx32, (ib + 1) * 4 + r);
                    const int d = __shfl_sync(0xffffffffu, idx32, 16 + (ib + 1) * 4 + r);
                    ap[nxt][r] = *(const uint2*)(g_PdrugH + (size_t)s * HID + lane * 4);
                    qp[nxt][r] = *(const uint2*)(g_PdisH  + (size_t)d * HID + lane * 4);
                    sv[nxt][r] = g_Sdrug[s] + g_Sdis[d];
                }
            }
            #pragma unroll
            for (int r = 0; r < 4; ++r) {
                const float2 a01 = __half22float2(*(const __half2*)&ap[cur][r].x);
                const float2 a23 = __half22float2(*(const __half2*)&ap[cur][r].y);
                const float2 q01 = __half22float2(*(const __half2*)&qp[cur][r].x);
                const float2 q23 = __half22float2(*(const __half2*)&qp[cur][r].y);
                float v[4];
                v[0] = a01.x + q01.x;
                v[1] = a01.y + q01.y;
                v[2] = a23.x + q23.x;
                v[3] = a23.y + q23.y;
                // mean from precomputed node sums (no shuffle)
                const float mu = sv[cur][r] * (1.0f / HID);
                float s2r = v[0]*v[0] + v[1]*v[1] + v[2]*v[2] + v[3]*v[3];
                #pragma unroll
                for (int m = 16; m > 0; m >>= 1)
                    s2r += __shfl_xor_sync(0xffffffffu, s2r, m);
                const float var = s2r * (1.0f / HID) - mu * mu;
                const float rs  = rsqrtf(var + 1e-5f);
                float h0 = gelu_fast((v[0] - mu) * rs * gg.x + ee.x);
                float h1 = gelu_fast((v[1] - mu) * rs * gg.y + ee.y);
                float h2 = gelu_fast((v[2] - mu) * rs * gg.z + ee.z);
                float h3 = gelu_fast((v[3] - mu) * rs * gg.w + ee.w);
                __half2 p0 = __floats2half2_rn(h0, h1);
                __half2 p1 = __floats2half2_rn(h2, h3);
                uint2 pk;
                pk.x = *reinterpret_cast<uint32_t*>(&p0);
                pk.y = *reinterpret_cast<uint32_t*>(&p1);
                *(uint2*)(As + (r0 + ib * 4 + r) * APITCH + lane * 4) = pk;
            }
        }
    }
    __syncwarp();   // A rows are warp-private

    // ---------------- Phase 2: HMMA m16n8k16; A scalar LDS, B LDS.64 -------
    const int gid = lane >> 2, tig = lane & 3;

    float acc[8][4];
    #pragma unroll
    for (int nt = 0; nt < 8; ++nt)
        #pragma unroll
        for (int j = 0; j < 4; ++j) acc[nt][j] = 0.0f;

    #pragma unroll
    for (int kt = 0; kt < 8; ++kt) {
        const int k0 = kt * 16;
        const uint32_t* arow0 = (const uint32_t*)(As + (r0 + gid) * APITCH + k0);
        const uint32_t* arow8 = (const uint32_t*)(As + (r0 + gid + 8) * APITCH + k0);
        uint32_t a0 = arow0[tig];
        uint32_t a1 = arow8[tig];
        uint32_t a2 = arow0[tig + 4];
        uint32_t a3 = arow8[tig + 4];
        #pragma unroll
        for (int nt = 0; nt < 8; ++nt) {
            const uint2 bw = Bp[(nt * 8 + kt) * 32 + lane];
            asm volatile(
                "mma.sync.aligned.m16n8k16.row.col.f32.f16.f16.f32 "
                "{%0,%1,%2,%3}, {%4,%5,%6,%7}, {%8,%9}, {%0,%1,%2,%3};"
                : "+f"(acc[nt][0]), "+f"(acc[nt][1]), "+f"(acc[nt][2]), "+f"(acc[nt][3])
                : "r"(a0), "r"(a1), "r"(a2), "r"(a3), "r"(bw.x), "r"(bw.y));
        }
    }

    // ---------------- Phase 3: +b2 (in acc) ; LN(64) ; GELU ; dot(W3)+b3 ---
    float s1a = 0.f, s2a = 0.f, s1b = 0.f, s2b = 0.f;
    #pragma unroll
    for (int nt = 0; nt < 8; ++nt) {
        #pragma unroll
        for (int j = 0; j < 2; ++j) {
            const float bb = b2s[nt * 8 + 2 * tig + j];
            acc[nt][j]     += bb;
            acc[nt][2 + j] += bb;
            const float tA = acc[nt][j];
            const float tB = acc[nt][2 + j];
            s1a += tA; s2a += tA * tA;
            s1b += tB; s2b += tB * tB;
        }
    }
    #pragma unroll
    for (int m = 1; m <= 2; m <<= 1) {
        s1a += __shfl_xor_sync(0xffffffffu, s1a, m);
        s2a += __shfl_xor_sync(0xffffffffu, s2a, m);
        s1b += __shfl_xor_sync(0xffffffffu, s1b, m);
        s2b += __shfl_xor_sync(0xffffffffu, s2b, m);
    }
    const float muA = s1a * (1.0f / HID2);
    const float rsA = rsqrtf(s2a * (1.0f / HID2) - muA * muA + 1e-5f);
    const float muB = s1b * (1.0f / HID2);
    const float rsB = rsqrtf(s2b * (1.0f / HID2) - muB * muB + 1e-5f);

    float dotA = 0.f, dotB = 0.f;
    #pragma unroll
    for (int nt = 0; nt < 8; ++nt) {
        #pragma unroll
        for (int j = 0; j < 2; ++j) {
            const int col = nt * 8 + 2 * tig + j;
            const float gg = g2s[col], be = be2s[col], ww = w3s[col];
            dotA = fmaf(gelu_fast((acc[nt][j]     - muA) * rsA * gg + be), ww, dotA);
            dotB = fmaf(gelu_fast((acc[nt][2 + j] - muB) * rsB * gg + be), ww, dotB);
        }
    }
    #pragma unroll
    for (int m = 1; m <= 2; m <<= 1) {
        dotA += __shfl_xor_sync(0xffffffffu, dotA, m);
        dotB += __shfl_xor_sync(0xffffffffu, dotB, m);
    }

    if (tig == 0) {
        const float b3v = b3[0];
        const int eA = e0 + r0 + gid;
        const int eB = eA + 8;
        if (eA < E) out[eA] = dotA + b3v;
        if (eB < E) out[eB] = dotB + b3v;
    }
}

// ---------------------------------------------------------------------------
extern "C" void kernel_launch(void* const* d_in, const int* in_sizes, int n_in,
                              void* d_out, int out_size)
{
    const float* drug = (const float*)d_in[0];
    const float* dis  = (const float*)d_in[1];
    const int*   src  = (const int*)  d_in[2];
    const int*   dst  = (const int*)  d_in[3];
    const float* W1   = (const float*)d_in[4];
    const float* b1   = (const float*)d_in[5];
    const float* g1   = (const float*)d_in[6];
    const float* be1  = (const float*)d_in[7];
    const float* W2   = (const float*)d_in[8];
    const float* b2   = (const float*)d_in[9];
    const float* g2   = (const float*)d_in[10];
    const float* be2  = (const float*)d_in[11];
    const float* W3   = (const float*)d_in[12];
    const float* b3   = (const float*)d_in[13];
    float* out = (float*)d_out;

    const int n_drug = in_sizes[0] / FEAT;
    const int n_dis  = in_sizes[1] / FEAT;
    const int E      = in_sizes[2];

    const int nmax = n_drug > n_dis ? n_drug : n_dis;
    dim3 pgrid((nmax + 31) / 32 + 1, 2);    // +1 block row for the W2 permute
    precompute_kernel<<<pgrid, THREADS>>>(drug, dis, W1, b1, W2, n_drug, n_dis);

    cudaFuncSetAttribute(edge_kernel, cudaFuncAttributeMaxDynamicSharedMemorySize, SM_TOTAL);
    const int blocks = (E + BM - 1) / BM;
    edge_kernel<<<blocks, THREADS, SM_TOTAL>>>(
        src, dst, g1, be1, b2, g2, be2, W3, b3, out, E);
}